// round 5
// baseline (speedup 1.0000x reference)
#include <cuda_runtime.h>

// Problem dims
#define BATCH 16
#define NN    2048          // nodes
#define EE    2048          // hyperedges
#define FF    256           // features

// Scratch: ne (8M) + xtoE (8M) + EtoX (8M) + colsum (32K) + rowsum (32K) floats
__device__ float g_scratch[3 * 8388608 + 2 * 32768];

// ---------------------------------------------------------------------------
// Sum kernels: rowsum[b][n] = sum_e H[b][n][e]; colsum[b][e] = sum_n H[b][n][e]
// ---------------------------------------------------------------------------
__global__ void rowsum_kernel(const float* __restrict__ H, float* __restrict__ rowsum) {
    // one warp per row; 8 warps per block; B*N rows total
    int warp = blockIdx.x * 8 + (threadIdx.x >> 5);
    int lane = threadIdx.x & 31;
    const float* row = H + (size_t)warp * EE;
    float s = 0.f;
    #pragma unroll 8
    for (int i = lane; i < EE; i += 32) s += row[i];
    #pragma unroll
    for (int o = 16; o > 0; o >>= 1) s += __shfl_xor_sync(0xffffffffu, s, o);
    if (lane == 0) rowsum[warp] = s;
}

__global__ void colsum_kernel(const float* __restrict__ H, float* __restrict__ colsum) {
    int b = blockIdx.y;
    int e = blockIdx.x * 256 + threadIdx.x;
    const float* base = H + (size_t)b * NN * EE + e;
    float s = 0.f;
    #pragma unroll 4
    for (int n = 0; n < NN; ++n) s += base[(size_t)n * EE];
    colsum[b * EE + e] = s;
}

// ---------------------------------------------------------------------------
// GEMM configuration: 128x128 tile, BK=16, 8x8 per thread, 256 threads
// ---------------------------------------------------------------------------
#define BM 128
#define BN 128
#define BK 16
#define TM 8
#define TN 8
#define STR 132   // padded smem row stride (floats), keeps 16B alignment

// Big GEMM on H.
// TRANSA=1:  C[m][f] = (sum_k A[k][m] * B[k][f]) * scale(sums[m])   (x_to_E)
// TRANSA=0:  C[m][f] = (sum_k A[m][k] * B[k][f]) * scale(sums[m])   (E_to_x)
// Per batch: A = H[b] (2048x2048), B (2048x256), C (2048x256), sums (2048)
template <int TRANSA>
__global__ __launch_bounds__(256)
void gemm_big_kernel(const float* __restrict__ Hbase,
                     const float* __restrict__ Bmat,
                     const float* __restrict__ sums,
                     float* __restrict__ Cmat) {
    int b = blockIdx.z;
    const float* A  = Hbase + (size_t)b * NN * EE;
    const float* Bp = Bmat  + (size_t)b * 2048 * FF;
    const float* ss = sums  + b * 2048;
    float*       Cp = Cmat  + (size_t)b * 2048 * FF;

    int m0 = blockIdx.y * BM;
    int n0 = blockIdx.x * BN;
    int tid = threadIdx.x;
    int tx = tid & 15;         // 0..15 -> cols
    int ty = tid >> 4;         // 0..15 -> rows

    __shared__ float As[BK][STR];
    __shared__ float Bs[BK][STR];

    float acc[TM][TN];
    #pragma unroll
    for (int i = 0; i < TM; ++i)
        #pragma unroll
        for (int j = 0; j < TN; ++j) acc[i][j] = 0.f;

    const int K = 2048;
    for (int k0 = 0; k0 < K; k0 += BK) {
        // B tile: 16 x 128, contiguous along f
        #pragma unroll
        for (int r = 0; r < 2; ++r) {
            int i = tid + r * 256;
            int row = i >> 5, c4 = (i & 31) << 2;
            float4 v = *reinterpret_cast<const float4*>(&Bp[(size_t)(k0 + row) * FF + n0 + c4]);
            *reinterpret_cast<float4*>(&Bs[row][c4]) = v;
        }
        if (TRANSA) {
            // As[k][m] = H[k0+k][m0+m]  (contiguous along m)
            #pragma unroll
            for (int r = 0; r < 2; ++r) {
                int i = tid + r * 256;
                int row = i >> 5, c4 = (i & 31) << 2;
                float4 v = *reinterpret_cast<const float4*>(&A[(size_t)(k0 + row) * EE + m0 + c4]);
                *reinterpret_cast<float4*>(&As[row][c4]) = v;
            }
        } else {
            // As[k][m] = H[m0+m][k0+k]  (contiguous along k; transpose-store)
            #pragma unroll
            for (int r = 0; r < 2; ++r) {
                int i = tid + r * 256;
                int m = i >> 2, k4 = (i & 3) << 2;
                float4 v = *reinterpret_cast<const float4*>(&A[(size_t)(m0 + m) * EE + k0 + k4]);
                As[k4 + 0][m] = v.x; As[k4 + 1][m] = v.y;
                As[k4 + 2][m] = v.z; As[k4 + 3][m] = v.w;
            }
        }
        __syncthreads();

        #pragma unroll
        for (int k = 0; k < BK; ++k) {
            float4 a0 = *reinterpret_cast<const float4*>(&As[k][ty * TM]);
            float4 a1 = *reinterpret_cast<const float4*>(&As[k][ty * TM + 4]);
            float4 b0 = *reinterpret_cast<const float4*>(&Bs[k][tx * TN]);
            float4 b1 = *reinterpret_cast<const float4*>(&Bs[k][tx * TN + 4]);
            float a[TM] = {a0.x, a0.y, a0.z, a0.w, a1.x, a1.y, a1.z, a1.w};
            float bb[TN] = {b0.x, b0.y, b0.z, b0.w, b1.x, b1.y, b1.z, b1.w};
            #pragma unroll
            for (int i = 0; i < TM; ++i)
                #pragma unroll
                for (int j = 0; j < TN; ++j)
                    acc[i][j] = fmaf(a[i], bb[j], acc[i][j]);
        }
        __syncthreads();
    }

    // Epilogue: per-output-row safe-norm scaling
    #pragma unroll
    for (int i = 0; i < TM; ++i) {
        int m = m0 + ty * TM + i;
        float s = ss[m];
        float sc = (s > 0.f) ? (1.f / s) : 0.f;
        #pragma unroll
        for (int j = 0; j < TN; j += 4) {
            float4 v;
            v.x = acc[i][j + 0] * sc;
            v.y = acc[i][j + 1] * sc;
            v.z = acc[i][j + 2] * sc;
            v.w = acc[i][j + 3] * sc;
            *reinterpret_cast<float4*>(&Cp[(size_t)m * FF + n0 + tx * TN + j]) = v;
        }
    }
}

// Fused small GEMM: C[m][f] = relu( sum_{k<256} A1[m][k] W[k][f]
//                                 + sum_{k<256} A2[m][k] W[256+k][f]  (if HAS_A2)
//                                 + bias[f] )
// M = BATCH*2048 (batch flattened), lda = 256, W is (K_total x 256) row-major.
template <bool HAS_A2>
__global__ __launch_bounds__(256)
void gemm_fused_kernel(const float* __restrict__ A1,
                       const float* __restrict__ A2,
                       const float* __restrict__ W,
                       const float* __restrict__ bias,
                       float* __restrict__ C) {
    int m0 = blockIdx.y * BM;
    int n0 = blockIdx.x * BN;
    int tid = threadIdx.x;
    int tx = tid & 15;
    int ty = tid >> 4;

    __shared__ float As[BK][STR];
    __shared__ float Bs[BK][STR];

    float acc[TM][TN];
    #pragma unroll
    for (int i = 0; i < TM; ++i)
        #pragma unroll
        for (int j = 0; j < TN; ++j) acc[i][j] = 0.f;

    const int K = HAS_A2 ? 512 : 256;
    for (int k0 = 0; k0 < K; k0 += BK) {
        const float* Asrc;
        int kloc;
        if (!HAS_A2 || k0 < 256) { Asrc = A1; kloc = k0; }
        else                     { Asrc = A2; kloc = k0 - 256; }

        // A tile: contiguous along k (lda=256), transpose-store
        #pragma unroll
        for (int r = 0; r < 2; ++r) {
            int i = tid + r * 256;
            int m = i >> 2, k4 = (i & 3) << 2;
            float4 v = *reinterpret_cast<const float4*>(&Asrc[(size_t)(m0 + m) * FF + kloc + k4]);
            As[k4 + 0][m] = v.x; As[k4 + 1][m] = v.y;
            As[k4 + 2][m] = v.z; As[k4 + 3][m] = v.w;
        }
        // W tile: 16 x 128
        #pragma unroll
        for (int r = 0; r < 2; ++r) {
            int i = tid + r * 256;
            int row = i >> 5, c4 = (i & 31) << 2;
            float4 v = *reinterpret_cast<const float4*>(&W[(size_t)(k0 + row) * FF + n0 + c4]);
            *reinterpret_cast<float4*>(&Bs[row][c4]) = v;
        }
        __syncthreads();

        #pragma unroll
        for (int k = 0; k < BK; ++k) {
            float4 a0 = *reinterpret_cast<const float4*>(&As[k][ty * TM]);
            float4 a1 = *reinterpret_cast<const float4*>(&As[k][ty * TM + 4]);
            float4 b0 = *reinterpret_cast<const float4*>(&Bs[k][tx * TN]);
            float4 b1 = *reinterpret_cast<const float4*>(&Bs[k][tx * TN + 4]);
            float a[TM] = {a0.x, a0.y, a0.z, a0.w, a1.x, a1.y, a1.z, a1.w};
            float bb[TN] = {b0.x, b0.y, b0.z, b0.w, b1.x, b1.y, b1.z, b1.w};
            #pragma unroll
            for (int i = 0; i < TM; ++i)
                #pragma unroll
                for (int j = 0; j < TN; ++j)
                    acc[i][j] = fmaf(a[i], bb[j], acc[i][j]);
        }
        __syncthreads();
    }

    float bn[TN];
    #pragma unroll
    for (int j = 0; j < TN; ++j) bn[j] = bias[n0 + tx * TN + j];

    #pragma unroll
    for (int i = 0; i < TM; ++i) {
        int m = m0 + ty * TM + i;
        #pragma unroll
        for (int j = 0; j < TN; j += 4) {
            float4 v;
            v.x = fmaxf(acc[i][j + 0] + bn[j + 0], 0.f);
            v.y = fmaxf(acc[i][j + 1] + bn[j + 1], 0.f);
            v.z = fmaxf(acc[i][j + 2] + bn[j + 2], 0.f);
            v.w = fmaxf(acc[i][j + 3] + bn[j + 3], 0.f);
            *reinterpret_cast<float4*>(&C[(size_t)m * FF + n0 + tx * TN + j]) = v;
        }
    }
}

// ---------------------------------------------------------------------------
extern "C" void kernel_launch(void* const* d_in, const int* in_sizes, int n_in,
                              void* d_out, int out_size) {
    const float* H    = (const float*)d_in[0];
    const float* E    = (const float*)d_in[1];
    const float* x    = (const float*)d_in[2];
    const float* W_ne = (const float*)d_in[3];
    const float* b_ne = (const float*)d_in[4];
    const float* W_e  = (const float*)d_in[5];
    const float* b_e  = (const float*)d_in[6];
    const float* W_n  = (const float*)d_in[7];
    const float* b_n  = (const float*)d_in[8];

    float* out  = (float*)d_out;
    float* newE = out;                                   // (B, E, F)
    float* newx = out + (size_t)BATCH * EE * FF;         // (B, N, F)

    float* scratch = nullptr;
    cudaGetSymbolAddress((void**)&scratch, g_scratch);
    float* ne     = scratch;                 // (B, N, F)
    float* xtoE   = scratch + 8388608;       // (B, E, F)
    float* EtoX   = scratch + 16777216;      // (B, N, F)
    float* colsum = scratch + 25165824;      // (B, E)
    float* rowsum = colsum + BATCH * EE;     // (B, N)

    // 1) H reductions
    rowsum_kernel<<<BATCH * NN / 8, 256>>>(H, rowsum);
    colsum_kernel<<<dim3(EE / 256, BATCH), 256>>>(H, colsum);

    // 2) ne = relu(x @ W_ne + b_ne)
    gemm_fused_kernel<false><<<dim3(FF / BN, BATCH * NN / BM), 256>>>(
        x, nullptr, W_ne, b_ne, ne);

    // 3) x_to_E = colscale * (H^T @ ne)
    gemm_big_kernel<1><<<dim3(FF / BN, EE / BM, BATCH), 256>>>(H, ne, colsum, xtoE);

    // 4) new_E = relu([x_to_E, E] @ W_e + b_e)
    gemm_fused_kernel<true><<<dim3(FF / BN, BATCH * EE / BM), 256>>>(
        xtoE, E, W_e, b_e, newE);

    // 5) E_to_x = rowscale * (H @ new_E)
    gemm_big_kernel<0><<<dim3(FF / BN, NN / BM, BATCH), 256>>>(H, newE, rowsum, EtoX);

    // 6) new_x = relu([E_to_x, x] @ W_n + b_n)
    gemm_fused_kernel<true><<<dim3(FF / BN, BATCH * NN / BM), 256>>>(
        EtoX, x, W_n, b_n, newx);
}

// round 8
// speedup vs baseline: 2.3575x; 2.3575x over previous
#include <cuda_runtime.h>

// Problem dims
#define BATCH 16
#define NN    2048
#define EE    2048
#define FF    256

// Scratch: ne (8M) + xtoE (8M) + EtoX (8M) + colsum (32K) + rowsum (32K) floats
__device__ float g_scratch[3 * 8388608 + 2 * 32768];

// ---------------------------------------------------------------------------
// Sum kernels
// ---------------------------------------------------------------------------
__global__ void rowsum_kernel(const float* __restrict__ H, float* __restrict__ rowsum) {
    int warp = blockIdx.x * 8 + (threadIdx.x >> 5);
    int lane = threadIdx.x & 31;
    const float* row = H + (size_t)warp * EE;
    float s = 0.f;
    #pragma unroll 8
    for (int i = lane; i < EE; i += 32) s += row[i];
    #pragma unroll
    for (int o = 16; o > 0; o >>= 1) s += __shfl_xor_sync(0xffffffffu, s, o);
    if (lane == 0) rowsum[warp] = s;
}

__global__ void colsum_kernel(const float* __restrict__ H, float* __restrict__ colsum) {
    int b = blockIdx.y;
    int e = blockIdx.x * 256 + threadIdx.x;
    const float* base = H + (size_t)b * NN * EE + e;
    float s = 0.f;
    #pragma unroll 4
    for (int n = 0; n < NN; ++n) s += base[(size_t)n * EE];
    colsum[b * EE + e] = s;
}

// ---------------------------------------------------------------------------
// tf32 tensor-core GEMM machinery
// ---------------------------------------------------------------------------
#define BKT      32      // K tile
#define AKM_STR  136     // A stored [k][m] : stride ≡ 8 (mod 32) -> conflict-free frags
#define AMK_STR  36      // A stored [m][k] : stride ≡ 4 (mod 32) -> conflict-free frags
#define BB_STR   136     // B stored [k][n]

__device__ __forceinline__ float tf32r(float x) {
    unsigned u;
    asm("cvt.rna.tf32.f32 %0, %1;" : "=r"(u) : "f"(x));
    return __uint_as_float(u);
}

__device__ __forceinline__ void mma_tf32(float* c, const float* a, const float* b) {
    asm volatile(
        "mma.sync.aligned.m16n8k8.row.col.f32.tf32.tf32.f32 "
        "{%0,%1,%2,%3}, {%4,%5,%6,%7}, {%8,%9}, {%0,%1,%2,%3};\n"
        : "+f"(c[0]), "+f"(c[1]), "+f"(c[2]), "+f"(c[3])
        : "r"(__float_as_uint(a[0])), "r"(__float_as_uint(a[1])),
          "r"(__float_as_uint(a[2])), "r"(__float_as_uint(a[3])),
          "r"(__float_as_uint(b[0])), "r"(__float_as_uint(b[1])));
}

// Big GEMM on H (per batch: A = H[b] 2048x2048, B 2048x256, C 2048x256).
// TRANSA=1: C[m][f] = scale(sums[m]) * sum_k A[k][m] B[k][f]   (x_to_E)
// TRANSA=0: C[m][f] = scale(sums[m]) * sum_k A[m][k] B[k][f]   (E_to_x)
template <int TRANSA>
__global__ __launch_bounds__(256)
void gemm_big_tc(const float* __restrict__ Hbase, const float* __restrict__ Bmat,
                 const float* __restrict__ sums, float* __restrict__ Cmat) {
    extern __shared__ float sm[];
    constexpr int ASZ = TRANSA ? (BKT * AKM_STR) : (128 * AMK_STR);
    constexpr int BSZ = BKT * BB_STR;
    float* As = sm;              // [2][ASZ]
    float* Bs = sm + 2 * ASZ;    // [2][BSZ]

    int b = blockIdx.z;
    const float* A  = Hbase + (size_t)b * NN * EE;
    const float* Bp = Bmat  + (size_t)b * 2048 * FF;
    const float* ss = sums  + b * 2048;
    float*       Cp = Cmat  + (size_t)b * 2048 * FF;

    int m0 = blockIdx.y * 128, n0 = blockIdx.x * 128;
    int tid = threadIdx.x, warp = tid >> 5, lane = tid & 31;
    int wm = warp >> 2, wn = warp & 3;   // 2 x 4 warp grid, 64x32 per warp
    int g = lane >> 2, t = lane & 3;

    float acc[4][4][4];
    #pragma unroll
    for (int i = 0; i < 4; ++i)
        #pragma unroll
        for (int j = 0; j < 4; ++j)
            #pragma unroll
            for (int r = 0; r < 4; ++r) acc[i][j][r] = 0.f;

    float4 Ar[4], Br[4];

    auto load_tile = [&](int k0) {
        #pragma unroll
        for (int r = 0; r < 4; ++r) {
            int i = r * 256 + tid;
            if (TRANSA) {
                int ka = i >> 5, ca = (i & 31) << 2;
                Ar[r] = *reinterpret_cast<const float4*>(&A[(size_t)(k0 + ka) * EE + m0 + ca]);
            } else {
                int ma = i >> 3, ca = (i & 7) << 2;
                Ar[r] = *reinterpret_cast<const float4*>(&A[(size_t)(m0 + ma) * EE + k0 + ca]);
            }
            int kb = i >> 5, cb = (i & 31) << 2;
            Br[r] = *reinterpret_cast<const float4*>(&Bp[(size_t)(k0 + kb) * FF + n0 + cb]);
        }
    };

    auto store_tile = [&](int buf) {
        float* Ad = As + buf * ASZ;
        float* Bd = Bs + buf * BSZ;
        #pragma unroll
        for (int r = 0; r < 4; ++r) {
            int i = r * 256 + tid;
            float4 w;
            w.x = tf32r(Ar[r].x); w.y = tf32r(Ar[r].y);
            w.z = tf32r(Ar[r].z); w.w = tf32r(Ar[r].w);
            if (TRANSA) {
                int ka = i >> 5, ca = (i & 31) << 2;
                *reinterpret_cast<float4*>(&Ad[ka * AKM_STR + ca]) = w;
            } else {
                int ma = i >> 3, ca = (i & 7) << 2;
                *reinterpret_cast<float4*>(&Ad[ma * AMK_STR + ca]) = w;
            }
            float4 xv;
            xv.x = tf32r(Br[r].x); xv.y = tf32r(Br[r].y);
            xv.z = tf32r(Br[r].z); xv.w = tf32r(Br[r].w);
            int kb = i >> 5, cb = (i & 31) << 2;
            *reinterpret_cast<float4*>(&Bd[kb * BB_STR + cb]) = xv;
        }
    };

    auto compute = [&](int buf) {
        const float* Ad = As + buf * ASZ;
        const float* Bd = Bs + buf * BSZ;
        #pragma unroll
        for (int ks = 0; ks < 4; ++ks) {
            int kk = ks * 8;
            float af[4][4], bf[4][2];
            #pragma unroll
            for (int mt = 0; mt < 4; ++mt) {
                int mb = wm * 64 + mt * 16 + g;
                if (TRANSA) {
                    af[mt][0] = Ad[(kk + t) * AKM_STR + mb];
                    af[mt][1] = Ad[(kk + t) * AKM_STR + mb + 8];
                    af[mt][2] = Ad[(kk + t + 4) * AKM_STR + mb];
                    af[mt][3] = Ad[(kk + t + 4) * AKM_STR + mb + 8];
                } else {
                    af[mt][0] = Ad[mb * AMK_STR + kk + t];
                    af[mt][1] = Ad[(mb + 8) * AMK_STR + kk + t];
                    af[mt][2] = Ad[mb * AMK_STR + kk + t + 4];
                    af[mt][3] = Ad[(mb + 8) * AMK_STR + kk + t + 4];
                }
            }
            #pragma unroll
            for (int nt = 0; nt < 4; ++nt) {
                int nb = wn * 32 + nt * 8 + g;
                bf[nt][0] = Bd[(kk + t) * BB_STR + nb];
                bf[nt][1] = Bd[(kk + t + 4) * BB_STR + nb];
            }
            #pragma unroll
            for (int mt = 0; mt < 4; ++mt)
                #pragma unroll
                for (int nt = 0; nt < 4; ++nt)
                    mma_tf32(acc[mt][nt], af[mt], bf[nt]);
        }
    };

    const int T = 2048 / BKT;
    load_tile(0);
    store_tile(0);
    __syncthreads();
    int buf = 0;
    #pragma unroll 1
    for (int it = 0; it < T; ++it) {
        if (it + 1 < T) load_tile((it + 1) * BKT);
        compute(buf);
        if (it + 1 < T) { store_tile(buf ^ 1); __syncthreads(); buf ^= 1; }
    }

    // Epilogue: per-output-row safe-norm scaling
    #pragma unroll
    for (int mt = 0; mt < 4; ++mt) {
        int m = m0 + wm * 64 + mt * 16 + g;
        float s0 = ss[m];     float sc0 = s0 > 0.f ? 1.f / s0 : 0.f;
        float s1 = ss[m + 8]; float sc1 = s1 > 0.f ? 1.f / s1 : 0.f;
        #pragma unroll
        for (int nt = 0; nt < 4; ++nt) {
            int n = n0 + wn * 32 + nt * 8 + 2 * t;
            float2 v0 = make_float2(acc[mt][nt][0] * sc0, acc[mt][nt][1] * sc0);
            float2 v1 = make_float2(acc[mt][nt][2] * sc1, acc[mt][nt][3] * sc1);
            *reinterpret_cast<float2*>(&Cp[(size_t)m * FF + n]) = v0;
            *reinterpret_cast<float2*>(&Cp[(size_t)(m + 8) * FF + n]) = v1;
        }
    }
}

// Fused small GEMM (tf32): C[m][f] = relu( [A1 | A2] @ W + bias ), lda = 256.
template <bool HAS_A2>
__global__ __launch_bounds__(256)
void gemm_fused_tc(const float* __restrict__ A1, const float* __restrict__ A2,
                   const float* __restrict__ W, const float* __restrict__ bias,
                   float* __restrict__ C) {
    extern __shared__ float sm[];
    constexpr int ASZ = 128 * AMK_STR;
    constexpr int BSZ = BKT * BB_STR;
    float* As = sm;
    float* Bs = sm + 2 * ASZ;

    int m0 = blockIdx.y * 128, n0 = blockIdx.x * 128;
    int tid = threadIdx.x, warp = tid >> 5, lane = tid & 31;
    int wm = warp >> 2, wn = warp & 3;
    int g = lane >> 2, t = lane & 3;

    float acc[4][4][4];
    #pragma unroll
    for (int i = 0; i < 4; ++i)
        #pragma unroll
        for (int j = 0; j < 4; ++j)
            #pragma unroll
            for (int r = 0; r < 4; ++r) acc[i][j][r] = 0.f;

    float4 Ar[4], Br[4];

    auto load_tile = [&](int k0) {
        const float* Asrc = (!HAS_A2 || k0 < 256) ? A1 : A2;
        int kloc = (!HAS_A2 || k0 < 256) ? k0 : (k0 - 256);
        #pragma unroll
        for (int r = 0; r < 4; ++r) {
            int i = r * 256 + tid;
            int ma = i >> 3, ca = (i & 7) << 2;
            Ar[r] = *reinterpret_cast<const float4*>(&Asrc[(size_t)(m0 + ma) * FF + kloc + ca]);
            int kb = i >> 5, cb = (i & 31) << 2;
            Br[r] = *reinterpret_cast<const float4*>(&W[(size_t)(k0 + kb) * FF + n0 + cb]);
        }
    };

    auto store_tile = [&](int buf) {
        float* Ad = As + buf * ASZ;
        float* Bd = Bs + buf * BSZ;
        #pragma unroll
        for (int r = 0; r < 4; ++r) {
            int i = r * 256 + tid;
            float4 w;
            w.x = tf32r(Ar[r].x); w.y = tf32r(Ar[r].y);
            w.z = tf32r(Ar[r].z); w.w = tf32r(Ar[r].w);
            int ma = i >> 3, ca = (i & 7) << 2;
            *reinterpret_cast<float4*>(&Ad[ma * AMK_STR + ca]) = w;
            float4 xv;
            xv.x = tf32r(Br[r].x); xv.y = tf32r(Br[r].y);
            xv.z = tf32r(Br[r].z); xv.w = tf32r(Br[r].w);
            int kb = i >> 5, cb = (i & 31) << 2;
            *reinterpret_cast<float4*>(&Bd[kb * BB_STR + cb]) = xv;
        }
    };

    auto compute = [&](int buf) {
        const float* Ad = As + buf * ASZ;
        const float* Bd = Bs + buf * BSZ;
        #pragma unroll
        for (int ks = 0; ks < 4; ++ks) {
            int kk = ks * 8;
            float af[4][4], bf[4][2];
            #pragma unroll
            for (int mt = 0; mt < 4; ++mt) {
                int mb = wm * 64 + mt * 16 + g;
                af[mt][0] = Ad[mb * AMK_STR + kk + t];
                af[mt][1] = Ad[(mb + 8) * AMK_STR + kk + t];
                af[mt][2] = Ad[mb * AMK_STR + kk + t + 4];
                af[mt][3] = Ad[(mb + 8) * AMK_STR + kk + t + 4];
            }
            #pragma unroll
            for (int nt = 0; nt < 4; ++nt) {
                int nb = wn * 32 + nt * 8 + g;
                bf[nt][0] = Bd[(kk + t) * BB_STR + nb];
                bf[nt][1] = Bd[(kk + t + 4) * BB_STR + nb];
            }
            #pragma unroll
            for (int mt = 0; mt < 4; ++mt)
                #pragma unroll
                for (int nt = 0; nt < 4; ++nt)
                    mma_tf32(acc[mt][nt], af[mt], bf[nt]);
        }
    };

    const int K = HAS_A2 ? 512 : 256;
    const int T = K / BKT;
    load_tile(0);
    store_tile(0);
    __syncthreads();
    int buf = 0;
    #pragma unroll 1
    for (int it = 0; it < T; ++it) {
        if (it + 1 < T) load_tile((it + 1) * BKT);
        compute(buf);
        if (it + 1 < T) { store_tile(buf ^ 1); __syncthreads(); buf ^= 1; }
    }

    // Epilogue: bias + relu
    #pragma unroll
    for (int nt = 0; nt < 4; ++nt) {
        int n = n0 + wn * 32 + nt * 8 + 2 * t;
        float bv0 = bias[n], bv1 = bias[n + 1];
        #pragma unroll
        for (int mt = 0; mt < 4; ++mt) {
            int m = m0 + wm * 64 + mt * 16 + g;
            float2 v0 = make_float2(fmaxf(acc[mt][nt][0] + bv0, 0.f),
                                    fmaxf(acc[mt][nt][1] + bv1, 0.f));
            float2 v1 = make_float2(fmaxf(acc[mt][nt][2] + bv0, 0.f),
                                    fmaxf(acc[mt][nt][3] + bv1, 0.f));
            *reinterpret_cast<float2*>(&C[(size_t)m * FF + n]) = v0;
            *reinterpret_cast<float2*>(&C[(size_t)(m + 8) * FF + n]) = v1;
        }
    }
}

// ---------------------------------------------------------------------------
extern "C" void kernel_launch(void* const* d_in, const int* in_sizes, int n_in,
                              void* d_out, int out_size) {
    const float* H    = (const float*)d_in[0];
    const float* E    = (const float*)d_in[1];
    const float* x    = (const float*)d_in[2];
    const float* W_ne = (const float*)d_in[3];
    const float* b_ne = (const float*)d_in[4];
    const float* W_e  = (const float*)d_in[5];
    const float* b_e  = (const float*)d_in[6];
    const float* W_n  = (const float*)d_in[7];
    const float* b_n  = (const float*)d_in[8];

    float* out  = (float*)d_out;
    float* newE = out;
    float* newx = out + (size_t)BATCH * EE * FF;

    float* scratch = nullptr;
    cudaGetSymbolAddress((void**)&scratch, g_scratch);
    float* ne     = scratch;
    float* xtoE   = scratch + 8388608;
    float* EtoX   = scratch + 16777216;
    float* colsum = scratch + 25165824;
    float* rowsum = colsum + BATCH * EE;

    const int SMEM_KM = (2 * BKT * AKM_STR + 2 * BKT * BB_STR) * 4;   // 69632
    const int SMEM_MK = (2 * 128 * AMK_STR + 2 * BKT * BB_STR) * 4;   // 71680

    static bool attr_done = false;
    if (!attr_done) {
        cudaFuncSetAttribute(gemm_big_tc<1>, cudaFuncAttributeMaxDynamicSharedMemorySize, SMEM_KM);
        cudaFuncSetAttribute(gemm_big_tc<0>, cudaFuncAttributeMaxDynamicSharedMemorySize, SMEM_MK);
        cudaFuncSetAttribute(gemm_fused_tc<false>, cudaFuncAttributeMaxDynamicSharedMemorySize, SMEM_MK);
        cudaFuncSetAttribute(gemm_fused_tc<true>, cudaFuncAttributeMaxDynamicSharedMemorySize, SMEM_MK);
        attr_done = true;
    }

    // 1) H reductions
    rowsum_kernel<<<BATCH * NN / 8, 256>>>(H, rowsum);
    colsum_kernel<<<dim3(EE / 256, BATCH), 256>>>(H, colsum);

    // 2) ne = relu(x @ W_ne + b_ne)
    gemm_fused_tc<false><<<dim3(FF / 128, BATCH * NN / 128), 256, SMEM_MK>>>(
        x, nullptr, W_ne, b_ne, ne);

    // 3) x_to_E = colscale * (H^T @ ne)
    gemm_big_tc<1><<<dim3(FF / 128, EE / 128, BATCH), 256, SMEM_KM>>>(H, ne, colsum, xtoE);

    // 4) new_E = relu([x_to_E, E] @ W_e + b_e)
    gemm_fused_tc<true><<<dim3(FF / 128, BATCH * EE / 128), 256, SMEM_MK>>>(
        xtoE, E, W_e, b_e, newE);

    // 5) E_to_x = rowscale * (H @ new_E)
    gemm_big_tc<0><<<dim3(FF / 128, NN / 128, BATCH), 256, SMEM_MK>>>(H, newE, rowsum, EtoX);

    // 6) new_x = relu([E_to_x, x] @ W_n + b_n)
    gemm_fused_tc<true><<<dim3(FF / 128, BATCH * NN / 128), 256, SMEM_MK>>>(
        EtoX, x, W_n, b_n, newx);
}

// round 9
// speedup vs baseline: 2.3586x; 1.0005x over previous
#include <cuda_runtime.h>

// Problem dims
#define BATCH 16
#define NN    2048
#define EE    2048
#define FF    256

// Scratch: ne (8M) + xtoE (8M) + EtoX (8M) + colsum (32K) + rowsum (32K) floats
__device__ float g_scratch[3 * 8388608 + 2 * 32768];

// ---------------------------------------------------------------------------
// Sum kernels
// ---------------------------------------------------------------------------
__global__ void rowsum_kernel(const float* __restrict__ H, float* __restrict__ rowsum) {
    int warp = blockIdx.x * 8 + (threadIdx.x >> 5);
    int lane = threadIdx.x & 31;
    const float* row = H + (size_t)warp * EE;
    float s = 0.f;
    #pragma unroll 8
    for (int i = lane; i < EE; i += 32) s += row[i];
    #pragma unroll
    for (int o = 16; o > 0; o >>= 1) s += __shfl_xor_sync(0xffffffffu, s, o);
    if (lane == 0) rowsum[warp] = s;
}

__global__ void colsum_kernel(const float* __restrict__ H, float* __restrict__ colsum) {
    int b = blockIdx.y;
    int e = blockIdx.x * 256 + threadIdx.x;
    const float* base = H + (size_t)b * NN * EE + e;
    float s = 0.f;
    #pragma unroll 4
    for (int n = 0; n < NN; ++n) s += base[(size_t)n * EE];
    colsum[b * EE + e] = s;
}

// ---------------------------------------------------------------------------
// tf32 tensor-core GEMM machinery
// ---------------------------------------------------------------------------
#define BKT      32      // K tile
#define AKM_STR  136     // A stored [k][m] : stride ≡ 8 (mod 32) -> conflict-free frags
#define AMK_STR  36      // A stored [m][k] : stride ≡ 4 (mod 32) -> conflict-free frags
#define BB_STR   136     // B stored [k][n]

__device__ __forceinline__ float tf32r(float x) {
    unsigned u;
    asm("cvt.rna.tf32.f32 %0, %1;" : "=r"(u) : "f"(x));
    return __uint_as_float(u);
}

__device__ __forceinline__ void mma_tf32(float* c, const float* a, const float* b) {
    asm volatile(
        "mma.sync.aligned.m16n8k8.row.col.f32.tf32.tf32.f32 "
        "{%0,%1,%2,%3}, {%4,%5,%6,%7}, {%8,%9}, {%0,%1,%2,%3};\n"
        : "+f"(c[0]), "+f"(c[1]), "+f"(c[2]), "+f"(c[3])
        : "r"(__float_as_uint(a[0])), "r"(__float_as_uint(a[1])),
          "r"(__float_as_uint(a[2])), "r"(__float_as_uint(a[3])),
          "r"(__float_as_uint(b[0])), "r"(__float_as_uint(b[1])));
}

// Big GEMM on H (per batch: A = H[b] 2048x2048, B 2048x256, C 2048x256).
// TRANSA=1: C[m][f] = scale(sums[m]) * sum_k A[k][m] B[k][f]   (x_to_E)
// TRANSA=0: C[m][f] = scale(sums[m]) * sum_k A[m][k] B[k][f]   (E_to_x)
template <int TRANSA>
__global__ __launch_bounds__(256)
void gemm_big_tc(const float* __restrict__ Hbase, const float* __restrict__ Bmat,
                 const float* __restrict__ sums, float* __restrict__ Cmat) {
    extern __shared__ float sm[];
    constexpr int ASZ = TRANSA ? (BKT * AKM_STR) : (128 * AMK_STR);
    constexpr int BSZ = BKT * BB_STR;
    float* As = sm;              // [2][ASZ]
    float* Bs = sm + 2 * ASZ;    // [2][BSZ]

    int b = blockIdx.z;
    const float* A  = Hbase + (size_t)b * NN * EE;
    const float* Bp = Bmat  + (size_t)b * 2048 * FF;
    const float* ss = sums  + b * 2048;
    float*       Cp = Cmat  + (size_t)b * 2048 * FF;

    int m0 = blockIdx.y * 128, n0 = blockIdx.x * 128;
    int tid = threadIdx.x, warp = tid >> 5, lane = tid & 31;
    int wm = warp >> 2, wn = warp & 3;   // 2 x 4 warp grid, 64x32 per warp
    int g = lane >> 2, t = lane & 3;

    float acc[4][4][4];
    #pragma unroll
    for (int i = 0; i < 4; ++i)
        #pragma unroll
        for (int j = 0; j < 4; ++j)
            #pragma unroll
            for (int r = 0; r < 4; ++r) acc[i][j][r] = 0.f;

    float4 Ar[4], Br[4];

    auto load_tile = [&](int k0) {
        #pragma unroll
        for (int r = 0; r < 4; ++r) {
            int i = r * 256 + tid;
            if (TRANSA) {
                int ka = i >> 5, ca = (i & 31) << 2;
                Ar[r] = *reinterpret_cast<const float4*>(&A[(size_t)(k0 + ka) * EE + m0 + ca]);
            } else {
                int ma = i >> 3, ca = (i & 7) << 2;
                Ar[r] = *reinterpret_cast<const float4*>(&A[(size_t)(m0 + ma) * EE + k0 + ca]);
            }
            int kb = i >> 5, cb = (i & 31) << 2;
            Br[r] = *reinterpret_cast<const float4*>(&Bp[(size_t)(k0 + kb) * FF + n0 + cb]);
        }
    };

    auto store_tile = [&](int buf) {
        float* Ad = As + buf * ASZ;
        float* Bd = Bs + buf * BSZ;
        #pragma unroll
        for (int r = 0; r < 4; ++r) {
            int i = r * 256 + tid;
            float4 w;
            w.x = tf32r(Ar[r].x); w.y = tf32r(Ar[r].y);
            w.z = tf32r(Ar[r].z); w.w = tf32r(Ar[r].w);
            if (TRANSA) {
                int ka = i >> 5, ca = (i & 31) << 2;
                *reinterpret_cast<float4*>(&Ad[ka * AKM_STR + ca]) = w;
            } else {
                int ma = i >> 3, ca = (i & 7) << 2;
                *reinterpret_cast<float4*>(&Ad[ma * AMK_STR + ca]) = w;
            }
            float4 xv;
            xv.x = tf32r(Br[r].x); xv.y = tf32r(Br[r].y);
            xv.z = tf32r(Br[r].z); xv.w = tf32r(Br[r].w);
            int kb = i >> 5, cb = (i & 31) << 2;
            *reinterpret_cast<float4*>(&Bd[kb * BB_STR + cb]) = xv;
        }
    };

    auto compute = [&](int buf) {
        const float* Ad = As + buf * ASZ;
        const float* Bd = Bs + buf * BSZ;
        #pragma unroll
        for (int ks = 0; ks < 4; ++ks) {
            int kk = ks * 8;
            float af[4][4], bf[4][2];
            #pragma unroll
            for (int mt = 0; mt < 4; ++mt) {
                int mb = wm * 64 + mt * 16 + g;
                if (TRANSA) {
                    af[mt][0] = Ad[(kk + t) * AKM_STR + mb];
                    af[mt][1] = Ad[(kk + t) * AKM_STR + mb + 8];
                    af[mt][2] = Ad[(kk + t + 4) * AKM_STR + mb];
                    af[mt][3] = Ad[(kk + t + 4) * AKM_STR + mb + 8];
                } else {
                    af[mt][0] = Ad[mb * AMK_STR + kk + t];
                    af[mt][1] = Ad[(mb + 8) * AMK_STR + kk + t];
                    af[mt][2] = Ad[mb * AMK_STR + kk + t + 4];
                    af[mt][3] = Ad[(mb + 8) * AMK_STR + kk + t + 4];
                }
            }
            #pragma unroll
            for (int nt = 0; nt < 4; ++nt) {
                int nb = wn * 32 + nt * 8 + g;
                bf[nt][0] = Bd[(kk + t) * BB_STR + nb];
                bf[nt][1] = Bd[(kk + t + 4) * BB_STR + nb];
            }
            #pragma unroll
            for (int mt = 0; mt < 4; ++mt)
                #pragma unroll
                for (int nt = 0; nt < 4; ++nt)
                    mma_tf32(acc[mt][nt], af[mt], bf[nt]);
        }
    };

    const int T = 2048 / BKT;
    load_tile(0);
    store_tile(0);
    __syncthreads();
    int buf = 0;
    #pragma unroll 1
    for (int it = 0; it < T; ++it) {
        if (it + 1 < T) load_tile((it + 1) * BKT);
        compute(buf);
        if (it + 1 < T) { store_tile(buf ^ 1); __syncthreads(); buf ^= 1; }
    }

    // Epilogue: per-output-row safe-norm scaling
    #pragma unroll
    for (int mt = 0; mt < 4; ++mt) {
        int m = m0 + wm * 64 + mt * 16 + g;
        float s0 = ss[m];     float sc0 = s0 > 0.f ? 1.f / s0 : 0.f;
        float s1 = ss[m + 8]; float sc1 = s1 > 0.f ? 1.f / s1 : 0.f;
        #pragma unroll
        for (int nt = 0; nt < 4; ++nt) {
            int n = n0 + wn * 32 + nt * 8 + 2 * t;
            float2 v0 = make_float2(acc[mt][nt][0] * sc0, acc[mt][nt][1] * sc0);
            float2 v1 = make_float2(acc[mt][nt][2] * sc1, acc[mt][nt][3] * sc1);
            *reinterpret_cast<float2*>(&Cp[(size_t)m * FF + n]) = v0;
            *reinterpret_cast<float2*>(&Cp[(size_t)(m + 8) * FF + n]) = v1;
        }
    }
}

// Fused small GEMM (tf32): C[m][f] = relu( [A1 | A2] @ W + bias ), lda = 256.
template <bool HAS_A2>
__global__ __launch_bounds__(256)
void gemm_fused_tc(const float* __restrict__ A1, const float* __restrict__ A2,
                   const float* __restrict__ W, const float* __restrict__ bias,
                   float* __restrict__ C) {
    extern __shared__ float sm[];
    constexpr int ASZ = 128 * AMK_STR;
    constexpr int BSZ = BKT * BB_STR;
    float* As = sm;
    float* Bs = sm + 2 * ASZ;

    int m0 = blockIdx.y * 128, n0 = blockIdx.x * 128;
    int tid = threadIdx.x, warp = tid >> 5, lane = tid & 31;
    int wm = warp >> 2, wn = warp & 3;
    int g = lane >> 2, t = lane & 3;

    float acc[4][4][4];
    #pragma unroll
    for (int i = 0; i < 4; ++i)
        #pragma unroll
        for (int j = 0; j < 4; ++j)
            #pragma unroll
            for (int r = 0; r < 4; ++r) acc[i][j][r] = 0.f;

    float4 Ar[4], Br[4];

    auto load_tile = [&](int k0) {
        const float* Asrc = (!HAS_A2 || k0 < 256) ? A1 : A2;
        int kloc = (!HAS_A2 || k0 < 256) ? k0 : (k0 - 256);
        #pragma unroll
        for (int r = 0; r < 4; ++r) {
            int i = r * 256 + tid;
            int ma = i >> 3, ca = (i & 7) << 2;
            Ar[r] = *reinterpret_cast<const float4*>(&Asrc[(size_t)(m0 + ma) * FF + kloc + ca]);
            int kb = i >> 5, cb = (i & 31) << 2;
            Br[r] = *reinterpret_cast<const float4*>(&W[(size_t)(k0 + kb) * FF + n0 + cb]);
        }
    };

    auto store_tile = [&](int buf) {
        float* Ad = As + buf * ASZ;
        float* Bd = Bs + buf * BSZ;
        #pragma unroll
        for (int r = 0; r < 4; ++r) {
            int i = r * 256 + tid;
            float4 w;
            w.x = tf32r(Ar[r].x); w.y = tf32r(Ar[r].y);
            w.z = tf32r(Ar[r].z); w.w = tf32r(Ar[r].w);
            int ma = i >> 3, ca = (i & 7) << 2;
            *reinterpret_cast<float4*>(&Ad[ma * AMK_STR + ca]) = w;
            float4 xv;
            xv.x = tf32r(Br[r].x); xv.y = tf32r(Br[r].y);
            xv.z = tf32r(Br[r].z); xv.w = tf32r(Br[r].w);
            int kb = i >> 5, cb = (i & 31) << 2;
            *reinterpret_cast<float4*>(&Bd[kb * BB_STR + cb]) = xv;
        }
    };

    auto compute = [&](int buf) {
        const float* Ad = As + buf * ASZ;
        const float* Bd = Bs + buf * BSZ;
        #pragma unroll
        for (int ks = 0; ks < 4; ++ks) {
            int kk = ks * 8;
            float af[4][4], bf[4][2];
            #pragma unroll
            for (int mt = 0; mt < 4; ++mt) {
                int mb = wm * 64 + mt * 16 + g;
                af[mt][0] = Ad[mb * AMK_STR + kk + t];
                af[mt][1] = Ad[(mb + 8) * AMK_STR + kk + t];
                af[mt][2] = Ad[mb * AMK_STR + kk + t + 4];
                af[mt][3] = Ad[(mb + 8) * AMK_STR + kk + t + 4];
            }
            #pragma unroll
            for (int nt = 0; nt < 4; ++nt) {
                int nb = wn * 32 + nt * 8 + g;
                bf[nt][0] = Bd[(kk + t) * BB_STR + nb];
                bf[nt][1] = Bd[(kk + t + 4) * BB_STR + nb];
            }
            #pragma unroll
            for (int mt = 0; mt < 4; ++mt)
                #pragma unroll
                for (int nt = 0; nt < 4; ++nt)
                    mma_tf32(acc[mt][nt], af[mt], bf[nt]);
        }
    };

    const int K = HAS_A2 ? 512 : 256;
    const int T = K / BKT;
    load_tile(0);
    store_tile(0);
    __syncthreads();
    int buf = 0;
    #pragma unroll 1
    for (int it = 0; it < T; ++it) {
        if (it + 1 < T) load_tile((it + 1) * BKT);
        compute(buf);
        if (it + 1 < T) { store_tile(buf ^ 1); __syncthreads(); buf ^= 1; }
    }

    // Epilogue: bias + relu
    #pragma unroll
    for (int nt = 0; nt < 4; ++nt) {
        int n = n0 + wn * 32 + nt * 8 + 2 * t;
        float bv0 = bias[n], bv1 = bias[n + 1];
        #pragma unroll
        for (int mt = 0; mt < 4; ++mt) {
            int m = m0 + wm * 64 + mt * 16 + g;
            float2 v0 = make_float2(fmaxf(acc[mt][nt][0] + bv0, 0.f),
                                    fmaxf(acc[mt][nt][1] + bv1, 0.f));
            float2 v1 = make_float2(fmaxf(acc[mt][nt][2] + bv0, 0.f),
                                    fmaxf(acc[mt][nt][3] + bv1, 0.f));
            *reinterpret_cast<float2*>(&C[(size_t)m * FF + n]) = v0;
            *reinterpret_cast<float2*>(&C[(size_t)(m + 8) * FF + n]) = v1;
        }
    }
}

// ---------------------------------------------------------------------------
extern "C" void kernel_launch(void* const* d_in, const int* in_sizes, int n_in,
                              void* d_out, int out_size) {
    const float* H    = (const float*)d_in[0];
    const float* E    = (const float*)d_in[1];
    const float* x    = (const float*)d_in[2];
    const float* W_ne = (const float*)d_in[3];
    const float* b_ne = (const float*)d_in[4];
    const float* W_e  = (const float*)d_in[5];
    const float* b_e  = (const float*)d_in[6];
    const float* W_n  = (const float*)d_in[7];
    const float* b_n  = (const float*)d_in[8];

    float* out  = (float*)d_out;
    float* newE = out;
    float* newx = out + (size_t)BATCH * EE * FF;

    float* scratch = nullptr;
    cudaGetSymbolAddress((void**)&scratch, g_scratch);
    float* ne     = scratch;
    float* xtoE   = scratch + 8388608;
    float* EtoX   = scratch + 16777216;
    float* colsum = scratch + 25165824;
    float* rowsum = colsum + BATCH * EE;

    const int SMEM_KM = (2 * BKT * AKM_STR + 2 * BKT * BB_STR) * 4;   // 69632
    const int SMEM_MK = (2 * 128 * AMK_STR + 2 * BKT * BB_STR) * 4;   // 71680

    static bool attr_done = false;
    if (!attr_done) {
        cudaFuncSetAttribute(gemm_big_tc<1>, cudaFuncAttributeMaxDynamicSharedMemorySize, SMEM_KM);
        cudaFuncSetAttribute(gemm_big_tc<0>, cudaFuncAttributeMaxDynamicSharedMemorySize, SMEM_MK);
        cudaFuncSetAttribute(gemm_fused_tc<false>, cudaFuncAttributeMaxDynamicSharedMemorySize, SMEM_MK);
        cudaFuncSetAttribute(gemm_fused_tc<true>, cudaFuncAttributeMaxDynamicSharedMemorySize, SMEM_MK);
        attr_done = true;
    }

    // 1) H reductions
    rowsum_kernel<<<BATCH * NN / 8, 256>>>(H, rowsum);
    colsum_kernel<<<dim3(EE / 256, BATCH), 256>>>(H, colsum);

    // 2) ne = relu(x @ W_ne + b_ne)
    gemm_fused_tc<false><<<dim3(FF / 128, BATCH * NN / 128), 256, SMEM_MK>>>(
        x, nullptr, W_ne, b_ne, ne);

    // 3) x_to_E = colscale * (H^T @ ne)
    gemm_big_tc<1><<<dim3(FF / 128, EE / 128, BATCH), 256, SMEM_KM>>>(H, ne, colsum, xtoE);

    // 4) new_E = relu([x_to_E, E] @ W_e + b_e)
    gemm_fused_tc<true><<<dim3(FF / 128, BATCH * EE / 128), 256, SMEM_MK>>>(
        xtoE, E, W_e, b_e, newE);

    // 5) E_to_x = rowscale * (H @ new_E)
    gemm_big_tc<0><<<dim3(FF / 128, NN / 128, BATCH), 256, SMEM_MK>>>(H, newE, rowsum, EtoX);

    // 6) new_x = relu([E_to_x, x] @ W_n + b_n)
    gemm_fused_tc<true><<<dim3(FF / 128, BATCH * NN / 128), 256, SMEM_MK>>>(
        EtoX, x, W_n, b_n, newx);
}

// round 10
// speedup vs baseline: 3.3901x; 1.4373x over previous
#include <cuda_runtime.h>

// Problem dims
#define BATCH 16
#define NN    2048
#define EE    2048
#define FF    256

// Scratch: ne (8M) + xtoE (8M) + EtoX (8M) floats
__device__ float g_scratch[3 * 8388608];

// ---------------------------------------------------------------------------
// tf32 tensor-core GEMM machinery
// ---------------------------------------------------------------------------
#define BKT      32      // K tile
#define AKM_STR  136     // A stored [k][m] : stride ≡ 8 (mod 32) -> conflict-free frags
#define AMK_STR  36      // A stored [m][k] : stride ≡ 4 (mod 32) -> conflict-free frags
#define BB_STR   136     // B stored [k][n]

__device__ __forceinline__ float tf32r(float x) {
    unsigned u;
    asm("cvt.rna.tf32.f32 %0, %1;" : "=r"(u) : "f"(x));
    return __uint_as_float(u);
}

__device__ __forceinline__ void mma_tf32(float* c, const float* a, const float* b) {
    asm volatile(
        "mma.sync.aligned.m16n8k8.row.col.f32.tf32.tf32.f32 "
        "{%0,%1,%2,%3}, {%4,%5,%6,%7}, {%8,%9}, {%0,%1,%2,%3};\n"
        : "+f"(c[0]), "+f"(c[1]), "+f"(c[2]), "+f"(c[3])
        : "r"(__float_as_uint(a[0])), "r"(__float_as_uint(a[1])),
          "r"(__float_as_uint(a[2])), "r"(__float_as_uint(a[3])),
          "r"(__float_as_uint(b[0])), "r"(__float_as_uint(b[1])));
}

// Big GEMM on H (per batch: A = H[b] 2048x2048, B 2048x256, C 2048x256).
// TRANSA=1: C[m][f] = scale_m * sum_k A[k][m] B[k][f]   (x_to_E; scale = 1/colsum)
// TRANSA=0: C[m][f] = scale_m * sum_k A[m][k] B[k][f]   (E_to_x; scale = 1/rowsum)
// The norm sums are computed IN-KERNEL from the staged raw A values (each block
// sees all K for its m-range), so no separate reduction kernels are needed.
template <int TRANSA>
__global__ __launch_bounds__(256)
void gemm_big_tc(const float* __restrict__ Hbase, const float* __restrict__ Bmat,
                 float* __restrict__ Cmat) {
    extern __shared__ float sm[];
    constexpr int ASZ = TRANSA ? (BKT * AKM_STR) : (128 * AMK_STR);
    constexpr int BSZ = BKT * BB_STR;
    float* As = sm;              // [2][ASZ]
    float* Bs = sm + 2 * ASZ;    // [2][BSZ]
    __shared__ float red[8 * 128];   // per-warp-group partial sums -> inv scales

    int b = blockIdx.z;
    const float* A  = Hbase + (size_t)b * NN * EE;
    const float* Bp = Bmat  + (size_t)b * 2048 * FF;
    float*       Cp = Cmat  + (size_t)b * 2048 * FF;

    int m0 = blockIdx.y * 128, n0 = blockIdx.x * 128;
    int tid = threadIdx.x, warp = tid >> 5, lane = tid & 31;
    int wm = warp >> 2, wn = warp & 3;   // 2 x 4 warp grid, 64x32 per warp
    int g = lane >> 2, t = lane & 3;

    float acc[4][4][4];
    #pragma unroll
    for (int i = 0; i < 4; ++i)
        #pragma unroll
        for (int j = 0; j < 4; ++j)
            #pragma unroll
            for (int r = 0; r < 4; ++r) acc[i][j][r] = 0.f;

    float4 Ar[4], Br[4];
    float hsum[4] = {0.f, 0.f, 0.f, 0.f};   // raw-H partial sums for the norm

    auto load_tile = [&](int k0) {
        #pragma unroll
        for (int r = 0; r < 4; ++r) {
            int i = r * 256 + tid;
            if (TRANSA) {
                int ka = i >> 5, ca = (i & 31) << 2;
                Ar[r] = *reinterpret_cast<const float4*>(&A[(size_t)(k0 + ka) * EE + m0 + ca]);
            } else {
                int ma = i >> 3, ca = (i & 7) << 2;
                Ar[r] = *reinterpret_cast<const float4*>(&A[(size_t)(m0 + ma) * EE + k0 + ca]);
            }
            int kb = i >> 5, cb = (i & 31) << 2;
            Br[r] = *reinterpret_cast<const float4*>(&Bp[(size_t)(k0 + kb) * FF + n0 + cb]);
        }
    };

    auto store_tile = [&](int buf) {
        float* Ad = As + buf * ASZ;
        float* Bd = Bs + buf * BSZ;
        #pragma unroll
        for (int r = 0; r < 4; ++r) {
            int i = r * 256 + tid;
            // accumulate raw sums for the safe-norm (exactly once per tile)
            if (TRANSA) {
                hsum[0] += Ar[r].x; hsum[1] += Ar[r].y;
                hsum[2] += Ar[r].z; hsum[3] += Ar[r].w;
            } else {
                hsum[r] += Ar[r].x + Ar[r].y + Ar[r].z + Ar[r].w;
            }
            float4 w;
            w.x = tf32r(Ar[r].x); w.y = tf32r(Ar[r].y);
            w.z = tf32r(Ar[r].z); w.w = tf32r(Ar[r].w);
            if (TRANSA) {
                int ka = i >> 5, ca = (i & 31) << 2;
                *reinterpret_cast<float4*>(&Ad[ka * AKM_STR + ca]) = w;
            } else {
                int ma = i >> 3, ca = (i & 7) << 2;
                *reinterpret_cast<float4*>(&Ad[ma * AMK_STR + ca]) = w;
            }
            float4 xv;
            xv.x = tf32r(Br[r].x); xv.y = tf32r(Br[r].y);
            xv.z = tf32r(Br[r].z); xv.w = tf32r(Br[r].w);
            int kb = i >> 5, cb = (i & 31) << 2;
            *reinterpret_cast<float4*>(&Bd[kb * BB_STR + cb]) = xv;
        }
    };

    auto loadfrag = [&](const float* Ad, const float* Bd, int kk,
                        float (*af)[4], float (*bf)[2]) {
        #pragma unroll
        for (int mt = 0; mt < 4; ++mt) {
            int mb = wm * 64 + mt * 16 + g;
            if (TRANSA) {
                af[mt][0] = Ad[(kk + t) * AKM_STR + mb];
                af[mt][1] = Ad[(kk + t) * AKM_STR + mb + 8];
                af[mt][2] = Ad[(kk + t + 4) * AKM_STR + mb];
                af[mt][3] = Ad[(kk + t + 4) * AKM_STR + mb + 8];
            } else {
                af[mt][0] = Ad[mb * AMK_STR + kk + t];
                af[mt][1] = Ad[(mb + 8) * AMK_STR + kk + t];
                af[mt][2] = Ad[mb * AMK_STR + kk + t + 4];
                af[mt][3] = Ad[(mb + 8) * AMK_STR + kk + t + 4];
            }
        }
        #pragma unroll
        for (int nt = 0; nt < 4; ++nt) {
            int nb = wn * 32 + nt * 8 + g;
            bf[nt][0] = Bd[(kk + t) * BB_STR + nb];
            bf[nt][1] = Bd[(kk + t + 4) * BB_STR + nb];
        }
    };

    float af[2][4][4], bf[2][4][2];

    const int T = 2048 / BKT;
    load_tile(0);
    store_tile(0);
    __syncthreads();
    int buf = 0;
    #pragma unroll 1
    for (int it = 0; it < T; ++it) {
        if (it + 1 < T) load_tile((it + 1) * BKT);
        const float* Ad = As + buf * ASZ;
        const float* Bd = Bs + buf * BSZ;
        // software-pipelined fragment loop: load slice ks+1 while MMAing slice ks
        loadfrag(Ad, Bd, 0, af[0], bf[0]);
        #pragma unroll
        for (int ks = 0; ks < 4; ++ks) {
            if (ks < 3) loadfrag(Ad, Bd, (ks + 1) * 8, af[(ks + 1) & 1], bf[(ks + 1) & 1]);
            #pragma unroll
            for (int mt = 0; mt < 4; ++mt)
                #pragma unroll
                for (int nt = 0; nt < 4; ++nt)
                    mma_tf32(acc[mt][nt], af[ks & 1][mt], bf[ks & 1][nt]);
        }
        if (it + 1 < T) { store_tile(buf ^ 1); __syncthreads(); buf ^= 1; }
    }

    // Cross-thread reduction of the norm sums -> red[0..127] = inv scale per m
    __syncthreads();
    if (TRANSA) {
        #pragma unroll
        for (int j = 0; j < 4; ++j)
            red[warp * 128 + (lane << 2) + j] = hsum[j];
    } else {
        #pragma unroll
        for (int r = 0; r < 4; ++r)
            red[(tid & 7) * 128 + r * 32 + (tid >> 3)] = hsum[r];
    }
    __syncthreads();
    if (tid < 128) {
        float s = 0.f;
        #pragma unroll
        for (int w = 0; w < 8; ++w) s += red[w * 128 + tid];
        red[tid] = (s > 0.f) ? (1.f / s) : 0.f;
    }
    __syncthreads();

    // Epilogue: per-output-row safe-norm scaling
    #pragma unroll
    for (int mt = 0; mt < 4; ++mt) {
        int ml = wm * 64 + mt * 16 + g;
        int m  = m0 + ml;
        float sc0 = red[ml];
        float sc1 = red[ml + 8];
        #pragma unroll
        for (int nt = 0; nt < 4; ++nt) {
            int n = n0 + wn * 32 + nt * 8 + 2 * t;
            float2 v0 = make_float2(acc[mt][nt][0] * sc0, acc[mt][nt][1] * sc0);
            float2 v1 = make_float2(acc[mt][nt][2] * sc1, acc[mt][nt][3] * sc1);
            *reinterpret_cast<float2*>(&Cp[(size_t)m * FF + n]) = v0;
            *reinterpret_cast<float2*>(&Cp[(size_t)(m + 8) * FF + n]) = v1;
        }
    }
}

// Fused small GEMM (tf32): C[m][f] = relu( [A1 | A2] @ W + bias ), lda = 256.
template <bool HAS_A2>
__global__ __launch_bounds__(256)
void gemm_fused_tc(const float* __restrict__ A1, const float* __restrict__ A2,
                   const float* __restrict__ W, const float* __restrict__ bias,
                   float* __restrict__ C) {
    extern __shared__ float sm[];
    constexpr int ASZ = 128 * AMK_STR;
    constexpr int BSZ = BKT * BB_STR;
    float* As = sm;
    float* Bs = sm + 2 * ASZ;

    int m0 = blockIdx.y * 128, n0 = blockIdx.x * 128;
    int tid = threadIdx.x, warp = tid >> 5, lane = tid & 31;
    int wm = warp >> 2, wn = warp & 3;
    int g = lane >> 2, t = lane & 3;

    float acc[4][4][4];
    #pragma unroll
    for (int i = 0; i < 4; ++i)
        #pragma unroll
        for (int j = 0; j < 4; ++j)
            #pragma unroll
            for (int r = 0; r < 4; ++r) acc[i][j][r] = 0.f;

    float4 Ar[4], Br[4];

    auto load_tile = [&](int k0) {
        const float* Asrc = (!HAS_A2 || k0 < 256) ? A1 : A2;
        int kloc = (!HAS_A2 || k0 < 256) ? k0 : (k0 - 256);
        #pragma unroll
        for (int r = 0; r < 4; ++r) {
            int i = r * 256 + tid;
            int ma = i >> 3, ca = (i & 7) << 2;
            Ar[r] = *reinterpret_cast<const float4*>(&Asrc[(size_t)(m0 + ma) * FF + kloc + ca]);
            int kb = i >> 5, cb = (i & 31) << 2;
            Br[r] = *reinterpret_cast<const float4*>(&W[(size_t)(k0 + kb) * FF + n0 + cb]);
        }
    };

    auto store_tile = [&](int buf) {
        float* Ad = As + buf * ASZ;
        float* Bd = Bs + buf * BSZ;
        #pragma unroll
        for (int r = 0; r < 4; ++r) {
            int i = r * 256 + tid;
            float4 w;
            w.x = tf32r(Ar[r].x); w.y = tf32r(Ar[r].y);
            w.z = tf32r(Ar[r].z); w.w = tf32r(Ar[r].w);
            int ma = i >> 3, ca = (i & 7) << 2;
            *reinterpret_cast<float4*>(&Ad[ma * AMK_STR + ca]) = w;
            float4 xv;
            xv.x = tf32r(Br[r].x); xv.y = tf32r(Br[r].y);
            xv.z = tf32r(Br[r].z); xv.w = tf32r(Br[r].w);
            int kb = i >> 5, cb = (i & 31) << 2;
            *reinterpret_cast<float4*>(&Bd[kb * BB_STR + cb]) = xv;
        }
    };

    auto loadfrag = [&](const float* Ad, const float* Bd, int kk,
                        float (*af)[4], float (*bf)[2]) {
        #pragma unroll
        for (int mt = 0; mt < 4; ++mt) {
            int mb = wm * 64 + mt * 16 + g;
            af[mt][0] = Ad[mb * AMK_STR + kk + t];
            af[mt][1] = Ad[(mb + 8) * AMK_STR + kk + t];
            af[mt][2] = Ad[mb * AMK_STR + kk + t + 4];
            af[mt][3] = Ad[(mb + 8) * AMK_STR + kk + t + 4];
        }
        #pragma unroll
        for (int nt = 0; nt < 4; ++nt) {
            int nb = wn * 32 + nt * 8 + g;
            bf[nt][0] = Bd[(kk + t) * BB_STR + nb];
            bf[nt][1] = Bd[(kk + t + 4) * BB_STR + nb];
        }
    };

    float af[2][4][4], bf[2][4][2];

    const int K = HAS_A2 ? 512 : 256;
    const int T = K / BKT;
    load_tile(0);
    store_tile(0);
    __syncthreads();
    int buf = 0;
    #pragma unroll 1
    for (int it = 0; it < T; ++it) {
        if (it + 1 < T) load_tile((it + 1) * BKT);
        const float* Ad = As + buf * ASZ;
        const float* Bd = Bs + buf * BSZ;
        loadfrag(Ad, Bd, 0, af[0], bf[0]);
        #pragma unroll
        for (int ks = 0; ks < 4; ++ks) {
            if (ks < 3) loadfrag(Ad, Bd, (ks + 1) * 8, af[(ks + 1) & 1], bf[(ks + 1) & 1]);
            #pragma unroll
            for (int mt = 0; mt < 4; ++mt)
                #pragma unroll
                for (int nt = 0; nt < 4; ++nt)
                    mma_tf32(acc[mt][nt], af[ks & 1][mt], bf[ks & 1][nt]);
        }
        if (it + 1 < T) { store_tile(buf ^ 1); __syncthreads(); buf ^= 1; }
    }

    // Epilogue: bias + relu
    #pragma unroll
    for (int nt = 0; nt < 4; ++nt) {
        int n = n0 + wn * 32 + nt * 8 + 2 * t;
        float bv0 = bias[n], bv1 = bias[n + 1];
        #pragma unroll
        for (int mt = 0; mt < 4; ++mt) {
            int m = m0 + wm * 64 + mt * 16 + g;
            float2 v0 = make_float2(fmaxf(acc[mt][nt][0] + bv0, 0.f),
                                    fmaxf(acc[mt][nt][1] + bv1, 0.f));
            float2 v1 = make_float2(fmaxf(acc[mt][nt][2] + bv0, 0.f),
                                    fmaxf(acc[mt][nt][3] + bv1, 0.f));
            *reinterpret_cast<float2*>(&C[(size_t)m * FF + n]) = v0;
            *reinterpret_cast<float2*>(&C[(size_t)(m + 8) * FF + n]) = v1;
        }
    }
}

// ---------------------------------------------------------------------------
extern "C" void kernel_launch(void* const* d_in, const int* in_sizes, int n_in,
                              void* d_out, int out_size) {
    const float* H    = (const float*)d_in[0];
    const float* E    = (const float*)d_in[1];
    const float* x    = (const float*)d_in[2];
    const float* W_ne = (const float*)d_in[3];
    const float* b_ne = (const float*)d_in[4];
    const float* W_e  = (const float*)d_in[5];
    const float* b_e  = (const float*)d_in[6];
    const float* W_n  = (const float*)d_in[7];
    const float* b_n  = (const float*)d_in[8];

    float* out  = (float*)d_out;
    float* newE = out;
    float* newx = out + (size_t)BATCH * EE * FF;

    float* scratch = nullptr;
    cudaGetSymbolAddress((void**)&scratch, g_scratch);
    float* ne   = scratch;
    float* xtoE = scratch + 8388608;
    float* EtoX = scratch + 16777216;

    const int SMEM_KM = (2 * BKT * AKM_STR + 2 * BKT * BB_STR) * 4;   // 69632
    const int SMEM_MK = (2 * 128 * AMK_STR + 2 * BKT * BB_STR) * 4;   // 71680

    static bool attr_done = false;
    if (!attr_done) {
        cudaFuncSetAttribute(gemm_big_tc<1>, cudaFuncAttributeMaxDynamicSharedMemorySize, SMEM_KM);
        cudaFuncSetAttribute(gemm_big_tc<0>, cudaFuncAttributeMaxDynamicSharedMemorySize, SMEM_MK);
        cudaFuncSetAttribute(gemm_fused_tc<false>, cudaFuncAttributeMaxDynamicSharedMemorySize, SMEM_MK);
        cudaFuncSetAttribute(gemm_fused_tc<true>, cudaFuncAttributeMaxDynamicSharedMemorySize, SMEM_MK);
        attr_done = true;
    }

    // 1) ne = relu(x @ W_ne + b_ne)
    gemm_fused_tc<false><<<dim3(FF / 128, BATCH * NN / 128), 256, SMEM_MK>>>(
        x, nullptr, W_ne, b_ne, ne);

    // 2) x_to_E = colscale * (H^T @ ne)   [colsum fused in-kernel]
    gemm_big_tc<1><<<dim3(FF / 128, EE / 128, BATCH), 256, SMEM_KM>>>(H, ne, xtoE);

    // 3) new_E = relu([x_to_E, E] @ W_e + b_e)
    gemm_fused_tc<true><<<dim3(FF / 128, BATCH * EE / 128), 256, SMEM_MK>>>(
        xtoE, E, W_e, b_e, newE);

    // 4) E_to_x = rowscale * (H @ new_E)  [rowsum fused in-kernel]
    gemm_big_tc<0><<<dim3(FF / 128, NN / 128, BATCH), 256, SMEM_MK>>>(H, newE, EtoX);

    // 5) new_x = relu([E_to_x, x] @ W_n + b_n)
    gemm_fused_tc<true><<<dim3(FF / 128, BATCH * NN / 128), 256, SMEM_MK>>>(
        EtoX, x, W_n, b_n, newx);
}

// round 12
// speedup vs baseline: 3.8549x; 1.1371x over previous
#include <cuda_runtime.h>
#include <cstdint>

// Problem dims
#define BATCH 16
#define NN    2048
#define EE    2048
#define FF    256

// Scratch: ne (8M) + xtoE (8M) + EtoX (8M) floats
__device__ float g_scratch[3 * 8388608];

// ---------------------------------------------------------------------------
// tf32 tensor-core GEMM machinery (ldmatrix fragments)
// Smem layouts: A[m][k], B[n][k], both row stride STR=36 floats
// (36 ≡ 4 mod 32 -> conflict-free float4 STS and conflict-free 8-row ldmatrix)
// ---------------------------------------------------------------------------
#define BKT 32
#define STR 36
#define ASZ (128 * STR)     // 4608 floats per buffer
#define BSZ (128 * STR)

__device__ __forceinline__ float tf32r(float x) {
    unsigned u;
    asm("cvt.rna.tf32.f32 %0, %1;" : "=r"(u) : "f"(x));
    return __uint_as_float(u);
}

__device__ __forceinline__ void ldsm4(uint32_t* d, uint32_t addr) {
    asm volatile("ldmatrix.sync.aligned.m8n8.x4.shared.b16 {%0,%1,%2,%3}, [%4];"
                 : "=r"(d[0]), "=r"(d[1]), "=r"(d[2]), "=r"(d[3]) : "r"(addr));
}

__device__ __forceinline__ void mma_tf32(float* c, const uint32_t* a, const uint32_t* b) {
    asm volatile(
        "mma.sync.aligned.m16n8k8.row.col.f32.tf32.tf32.f32 "
        "{%0,%1,%2,%3}, {%4,%5,%6,%7}, {%8,%9}, {%0,%1,%2,%3};\n"
        : "+f"(c[0]), "+f"(c[1]), "+f"(c[2]), "+f"(c[3])
        : "r"(a[0]), "r"(a[1]), "r"(a[2]), "r"(a[3]), "r"(b[0]), "r"(b[1]));
}

// A-fragment ldmatrix lane offset: lanes 0-15 -> rows mb+(lane&15) col kk,
// lanes 16-31 -> rows mb+(lane&15) col kk+4.  (bytes)
__device__ __forceinline__ uint32_t offA_lane(int lane) {
    return (uint32_t)(((lane & 15) * STR + (lane >> 4) * 4) * 4);
}
// B-fragment (x4 covers nt pair): row nb + (lane>>4)*8 + (lane&7),
// col kk + ((lane>>3)&1)*4.  (bytes)
__device__ __forceinline__ uint32_t offB_lane(int lane) {
    return (uint32_t)((((lane >> 4) * 8 + (lane & 7)) * STR + ((lane >> 3) & 1) * 4) * 4);
}

// Big GEMM on H (per batch: A = H[b] 2048x2048, B 2048x256, C 2048x256).
// TRANSA=1: C[m][f] = scale_m * sum_k A[k][m] B[k][f]   (x_to_E; scale = 1/colsum)
// TRANSA=0: C[m][f] = scale_m * sum_k A[m][k] B[k][f]   (E_to_x; scale = 1/rowsum)
// Norm sums computed in-kernel from staged raw values.
template <int TRANSA>
__global__ __launch_bounds__(256, 2)
void gemm_big_tc(const float* __restrict__ Hbase, const float* __restrict__ Bmat,
                 float* __restrict__ Cmat) {
    extern __shared__ float sm[];
    float* Abuf = sm;                 // [2][ASZ]
    float* Bbuf = sm + 2 * ASZ;       // [2][BSZ]
    __shared__ float red[1024];

    int b = blockIdx.z;
    const float* A  = Hbase + (size_t)b * NN * EE;
    const float* Bp = Bmat  + (size_t)b * 2048 * FF;
    float*       Cp = Cmat  + (size_t)b * 2048 * FF;

    int m0 = blockIdx.y * 128, n0 = blockIdx.x * 128;
    int tid = threadIdx.x, warp = tid >> 5, lane = tid & 31;
    int wm = warp >> 2, wn = warp & 3;   // 2x4 warp grid, 64x32 per warp
    int g = lane >> 2, t = lane & 3;

    uint32_t su   = (uint32_t)__cvta_generic_to_shared(sm);
    uint32_t offA = offA_lane(lane);
    uint32_t offB = offB_lane(lane);

    // thread roles for transposed loads
    int mloc  = tid & 127;     // owned m (TRANSA=1) / n column
    int khalf = tid >> 7;      // 0 or 1

    float acc[4][4][4];
    #pragma unroll
    for (int i = 0; i < 4; ++i)
        #pragma unroll
        for (int j = 0; j < 4; ++j)
            #pragma unroll
            for (int r = 0; r < 4; ++r) acc[i][j][r] = 0.f;

    float4 Ar[4], Br[4];
    float hsum[4] = {0.f, 0.f, 0.f, 0.f};   // raw partial sums for the norm

    auto load_tile = [&](int k0) {
        #pragma unroll
        for (int r = 0; r < 4; ++r) {
            if (TRANSA) {
                // A gmem [k][m] m-contiguous -> 4x LDG.32 down k (transpose in regs)
                int kg = 2 * r + khalf;
                const float* p = &A[(size_t)(k0 + 4 * kg) * EE + m0 + mloc];
                Ar[r].x = p[0]; Ar[r].y = p[EE]; Ar[r].z = p[2 * EE]; Ar[r].w = p[3 * EE];
            } else {
                // A gmem [m][k] k-contiguous -> float4
                int ma = r * 32 + (tid >> 3), ca = (tid & 7) << 2;
                Ar[r] = *reinterpret_cast<const float4*>(&A[(size_t)(m0 + ma) * EE + k0 + ca]);
            }
            // B gmem [k][n] n-contiguous -> transpose in regs
            int kg = 2 * r + khalf;
            const float* q = &Bp[(size_t)(k0 + 4 * kg) * FF + n0 + mloc];
            Br[r].x = q[0]; Br[r].y = q[FF]; Br[r].z = q[2 * FF]; Br[r].w = q[3 * FF];
        }
    };

    auto store_tile = [&](int buf) {
        float* Ad = Abuf + buf * ASZ;
        float* Bd = Bbuf + buf * BSZ;
        #pragma unroll
        for (int r = 0; r < 4; ++r) {
            // raw sums for safe-norm (exactly once per tile)
            if (TRANSA) hsum[0] += Ar[r].x + Ar[r].y + Ar[r].z + Ar[r].w;
            else        hsum[r] += Ar[r].x + Ar[r].y + Ar[r].z + Ar[r].w;
            float4 w;
            w.x = tf32r(Ar[r].x); w.y = tf32r(Ar[r].y);
            w.z = tf32r(Ar[r].z); w.w = tf32r(Ar[r].w);
            if (TRANSA) {
                int kg = 2 * r + khalf;
                *reinterpret_cast<float4*>(&Ad[mloc * STR + 4 * kg]) = w;
            } else {
                int ma = r * 32 + (tid >> 3), ca = (tid & 7) << 2;
                *reinterpret_cast<float4*>(&Ad[ma * STR + ca]) = w;
            }
            float4 xv;
            xv.x = tf32r(Br[r].x); xv.y = tf32r(Br[r].y);
            xv.z = tf32r(Br[r].z); xv.w = tf32r(Br[r].w);
            int kg = 2 * r + khalf;
            *reinterpret_cast<float4*>(&Bd[mloc * STR + 4 * kg]) = xv;
        }
    };

    auto compute = [&](int buf) {
        uint32_t aB = su + (buf * ASZ) * 4;
        uint32_t bB = su + (2 * ASZ + buf * BSZ) * 4;
        #pragma unroll
        for (int ks = 0; ks < 4; ++ks) {
            uint32_t kkb = ks * 8 * 4;
            uint32_t a[4][4], bb[2][4];
            #pragma unroll
            for (int p = 0; p < 2; ++p)
                ldsm4(bb[p], bB + (uint32_t)((wn * 32 + p * 16) * STR * 4) + kkb + offB);
            #pragma unroll
            for (int mt = 0; mt < 4; ++mt)
                ldsm4(a[mt], aB + (uint32_t)((wm * 64 + mt * 16) * STR * 4) + kkb + offA);
            #pragma unroll
            for (int mt = 0; mt < 4; ++mt) {
                mma_tf32(acc[mt][0], a[mt], &bb[0][0]);
                mma_tf32(acc[mt][1], a[mt], &bb[0][2]);
                mma_tf32(acc[mt][2], a[mt], &bb[1][0]);
                mma_tf32(acc[mt][3], a[mt], &bb[1][2]);
            }
        }
    };

    const int T = 2048 / BKT;
    load_tile(0);
    store_tile(0);
    __syncthreads();
    int buf = 0;
    #pragma unroll 1
    for (int it = 0; it < T; ++it) {
        if (it + 1 < T) load_tile((it + 1) * BKT);
        compute(buf);
        if (it + 1 < T) { store_tile(buf ^ 1); __syncthreads(); buf ^= 1; }
    }

    // Reduce norm sums -> red[0..127] = inv scale per local m
    __syncthreads();
    if (TRANSA) {
        red[khalf * 128 + mloc] = hsum[0];
        __syncthreads();
        if (tid < 128) {
            float s = red[tid] + red[128 + tid];
            red[tid] = (s > 0.f) ? (1.f / s) : 0.f;
        }
    } else {
        #pragma unroll
        for (int r = 0; r < 4; ++r)
            red[(tid & 7) * 128 + r * 32 + (tid >> 3)] = hsum[r];
        __syncthreads();
        if (tid < 128) {
            float s = 0.f;
            #pragma unroll
            for (int w = 0; w < 8; ++w) s += red[w * 128 + tid];
            red[tid] = (s > 0.f) ? (1.f / s) : 0.f;
        }
    }
    __syncthreads();

    // Epilogue: per-output-row safe-norm scaling
    #pragma unroll
    for (int mt = 0; mt < 4; ++mt) {
        int ml = wm * 64 + mt * 16 + g;
        int m  = m0 + ml;
        float sc0 = red[ml];
        float sc1 = red[ml + 8];
        #pragma unroll
        for (int nt = 0; nt < 4; ++nt) {
            int n = n0 + wn * 32 + nt * 8 + 2 * t;
            float2 v0 = make_float2(acc[mt][nt][0] * sc0, acc[mt][nt][1] * sc0);
            float2 v1 = make_float2(acc[mt][nt][2] * sc1, acc[mt][nt][3] * sc1);
            *reinterpret_cast<float2*>(&Cp[(size_t)m * FF + n]) = v0;
            *reinterpret_cast<float2*>(&Cp[(size_t)(m + 8) * FF + n]) = v1;
        }
    }
}

// Fused small GEMM (tf32): C[m][f] = relu( [A1 | A2] @ W + bias ), lda = 256.
template <bool HAS_A2>
__global__ __launch_bounds__(256, 2)
void gemm_fused_tc(const float* __restrict__ A1, const float* __restrict__ A2,
                   const float* __restrict__ W, const float* __restrict__ bias,
                   float* __restrict__ C) {
    extern __shared__ float sm[];
    float* Abuf = sm;
    float* Bbuf = sm + 2 * ASZ;

    int m0 = blockIdx.y * 128, n0 = blockIdx.x * 128;
    int tid = threadIdx.x, warp = tid >> 5, lane = tid & 31;
    int wm = warp >> 2, wn = warp & 3;
    int g = lane >> 2, t = lane & 3;

    uint32_t su   = (uint32_t)__cvta_generic_to_shared(sm);
    uint32_t offA = offA_lane(lane);
    uint32_t offB = offB_lane(lane);

    int nloc  = tid & 127;
    int khalf = tid >> 7;

    float acc[4][4][4];
    #pragma unroll
    for (int i = 0; i < 4; ++i)
        #pragma unroll
        for (int j = 0; j < 4; ++j)
            #pragma unroll
            for (int r = 0; r < 4; ++r) acc[i][j][r] = 0.f;

    float4 Ar[4], Br[4];

    auto load_tile = [&](int k0) {
        const float* Asrc = (!HAS_A2 || k0 < 256) ? A1 : A2;
        int kloc = (!HAS_A2 || k0 < 256) ? k0 : (k0 - 256);
        #pragma unroll
        for (int r = 0; r < 4; ++r) {
            int ma = r * 32 + (tid >> 3), ca = (tid & 7) << 2;
            Ar[r] = *reinterpret_cast<const float4*>(&Asrc[(size_t)(m0 + ma) * FF + kloc + ca]);
            int kg = 2 * r + khalf;
            const float* q = &W[(size_t)(k0 + 4 * kg) * FF + n0 + nloc];
            Br[r].x = q[0]; Br[r].y = q[FF]; Br[r].z = q[2 * FF]; Br[r].w = q[3 * FF];
        }
    };

    auto store_tile = [&](int buf) {
        float* Ad = Abuf + buf * ASZ;
        float* Bd = Bbuf + buf * BSZ;
        #pragma unroll
        for (int r = 0; r < 4; ++r) {
            float4 w;
            w.x = tf32r(Ar[r].x); w.y = tf32r(Ar[r].y);
            w.z = tf32r(Ar[r].z); w.w = tf32r(Ar[r].w);
            int ma = r * 32 + (tid >> 3), ca = (tid & 7) << 2;
            *reinterpret_cast<float4*>(&Ad[ma * STR + ca]) = w;
            float4 xv;
            xv.x = tf32r(Br[r].x); xv.y = tf32r(Br[r].y);
            xv.z = tf32r(Br[r].z); xv.w = tf32r(Br[r].w);
            int kg = 2 * r + khalf;
            *reinterpret_cast<float4*>(&Bd[nloc * STR + 4 * kg]) = xv;
        }
    };

    auto compute = [&](int buf) {
        uint32_t aB = su + (buf * ASZ) * 4;
        uint32_t bB = su + (2 * ASZ + buf * BSZ) * 4;
        #pragma unroll
        for (int ks = 0; ks < 4; ++ks) {
            uint32_t kkb = ks * 8 * 4;
            uint32_t a[4][4], bb[2][4];
            #pragma unroll
            for (int p = 0; p < 2; ++p)
                ldsm4(bb[p], bB + (uint32_t)((wn * 32 + p * 16) * STR * 4) + kkb + offB);
            #pragma unroll
            for (int mt = 0; mt < 4; ++mt)
                ldsm4(a[mt], aB + (uint32_t)((wm * 64 + mt * 16) * STR * 4) + kkb + offA);
            #pragma unroll
            for (int mt = 0; mt < 4; ++mt) {
                mma_tf32(acc[mt][0], a[mt], &bb[0][0]);
                mma_tf32(acc[mt][1], a[mt], &bb[0][2]);
                mma_tf32(acc[mt][2], a[mt], &bb[1][0]);
                mma_tf32(acc[mt][3], a[mt], &bb[1][2]);
            }
        }
    };

    const int K = HAS_A2 ? 512 : 256;
    const int T = K / BKT;
    load_tile(0);
    store_tile(0);
    __syncthreads();
    int buf = 0;
    #pragma unroll 1
    for (int it = 0; it < T; ++it) {
        if (it + 1 < T) load_tile((it + 1) * BKT);
        compute(buf);
        if (it + 1 < T) { store_tile(buf ^ 1); __syncthreads(); buf ^= 1; }
    }

    // Epilogue: bias + relu
    #pragma unroll
    for (int nt = 0; nt < 4; ++nt) {
        int n = n0 + wn * 32 + nt * 8 + 2 * t;
        float bv0 = bias[n], bv1 = bias[n + 1];
        #pragma unroll
        for (int mt = 0; mt < 4; ++mt) {
            int m = m0 + wm * 64 + mt * 16 + g;
            float2 v0 = make_float2(fmaxf(acc[mt][nt][0] + bv0, 0.f),
                                    fmaxf(acc[mt][nt][1] + bv1, 0.f));
            float2 v1 = make_float2(fmaxf(acc[mt][nt][2] + bv0, 0.f),
                                    fmaxf(acc[mt][nt][3] + bv1, 0.f));
            *reinterpret_cast<float2*>(&C[(size_t)m * FF + n]) = v0;
            *reinterpret_cast<float2*>(&C[(size_t)(m + 8) * FF + n]) = v1;
        }
    }
}

// ---------------------------------------------------------------------------
extern "C" void kernel_launch(void* const* d_in, const int* in_sizes, int n_in,
                              void* d_out, int out_size) {
    const float* H    = (const float*)d_in[0];
    const float* E    = (const float*)d_in[1];
    const float* x    = (const float*)d_in[2];
    const float* W_ne = (const float*)d_in[3];
    const float* b_ne = (const float*)d_in[4];
    const float* W_e  = (const float*)d_in[5];
    const float* b_e  = (const float*)d_in[6];
    const float* W_n  = (const float*)d_in[7];
    const float* b_n  = (const float*)d_in[8];

    float* out  = (float*)d_out;
    float* newE = out;
    float* newx = out + (size_t)BATCH * EE * FF;

    float* scratch = nullptr;
    cudaGetSymbolAddress((void**)&scratch, g_scratch);
    float* ne   = scratch;
    float* xtoE = scratch + 8388608;
    float* EtoX = scratch + 16777216;

    const int SMEM = (2 * ASZ + 2 * BSZ) * 4;   // 73728 bytes

    static bool attr_done = false;
    if (!attr_done) {
        cudaFuncSetAttribute(gemm_big_tc<1>, cudaFuncAttributeMaxDynamicSharedMemorySize, SMEM);
        cudaFuncSetAttribute(gemm_big_tc<0>, cudaFuncAttributeMaxDynamicSharedMemorySize, SMEM);
        cudaFuncSetAttribute(gemm_fused_tc<false>, cudaFuncAttributeMaxDynamicSharedMemorySize, SMEM);
        cudaFuncSetAttribute(gemm_fused_tc<true>, cudaFuncAttributeMaxDynamicSharedMemorySize, SMEM);
        attr_done = true;
    }

    // 1) ne = relu(x @ W_ne + b_ne)
    gemm_fused_tc<false><<<dim3(FF / 128, BATCH * NN / 128), 256, SMEM>>>(
        x, nullptr, W_ne, b_ne, ne);

    // 2) x_to_E = colscale * (H^T @ ne)   [colsum fused in-kernel]
    gemm_big_tc<1><<<dim3(FF / 128, EE / 128, BATCH), 256, SMEM>>>(H, ne, xtoE);

    // 3) new_E = relu([x_to_E, E] @ W_e + b_e)
    gemm_fused_tc<true><<<dim3(FF / 128, BATCH * EE / 128), 256, SMEM>>>(
        xtoE, E, W_e, b_e, newE);

    // 4) E_to_x = rowscale * (H @ new_E)  [rowsum fused in-kernel]
    gemm_big_tc<0><<<dim3(FF / 128, NN / 128, BATCH), 256, SMEM>>>(H, newE, EtoX);

    // 5) new_x = relu([E_to_x, x] @ W_n + b_n)
    gemm_fused_tc<true><<<dim3(FF / 128, BATCH * NN / 128), 256, SMEM>>>(
        EtoX, x, W_n, b_n, newx);
}

// round 15
// speedup vs baseline: 4.1528x; 1.0773x over previous
#include <cuda_runtime.h>
#include <cstdint>

// Problem dims
#define BATCH 16
#define NN    2048
#define EE    2048
#define FF    256

// Scratch: ne (8M) + xtoE (8M) + EtoX (8M) floats
__device__ float g_scratch[3 * 8388608];

// ---------------------------------------------------------------------------
// tf32 tensor-core GEMM machinery (ldmatrix fragments, legacy mma.sync path —
// tcgen05 is rejected by the harness's sm_103 (non-'a') ptxas target)
// Smem layouts: A[m][k], B[n][k], row stride STR=36 floats
// (36 ≡ 4 mod 32 -> conflict-free-enough float4 STS and 8-row ldmatrix)
// ---------------------------------------------------------------------------
#define STR 36

__device__ __forceinline__ float tf32r(float x) {
    unsigned u;
    asm("cvt.rna.tf32.f32 %0, %1;" : "=r"(u) : "f"(x));
    return __uint_as_float(u);
}

__device__ __forceinline__ void ldsm4(uint32_t* d, uint32_t addr) {
    asm volatile("ldmatrix.sync.aligned.m8n8.x4.shared.b16 {%0,%1,%2,%3}, [%4];"
                 : "=r"(d[0]), "=r"(d[1]), "=r"(d[2]), "=r"(d[3]) : "r"(addr));
}

__device__ __forceinline__ void mma_tf32(float* c, const uint32_t* a, const uint32_t* b) {
    asm volatile(
        "mma.sync.aligned.m16n8k8.row.col.f32.tf32.tf32.f32 "
        "{%0,%1,%2,%3}, {%4,%5,%6,%7}, {%8,%9}, {%0,%1,%2,%3};\n"
        : "+f"(c[0]), "+f"(c[1]), "+f"(c[2]), "+f"(c[3])
        : "r"(a[0]), "r"(a[1]), "r"(a[2]), "r"(a[3]), "r"(b[0]), "r"(b[1]));
}

// A-fragment ldmatrix lane offset: lanes 0-15 -> rows +(lane&15), col 0;
// lanes 16-31 -> same rows, col +4. (bytes)
__device__ __forceinline__ uint32_t offA_lane(int lane) {
    return (uint32_t)(((lane & 15) * STR + (lane >> 4) * 4) * 4);
}
// B-fragment (x4 covers an nt pair): row +(lane>>4)*8+(lane&7),
// col +((lane>>3)&1)*4. (bytes)
__device__ __forceinline__ uint32_t offB_lane(int lane) {
    return (uint32_t)((((lane >> 4) * 8 + (lane & 7)) * STR + ((lane >> 3) & 1) * 4) * 4);
}

// ===========================================================================
// Big GEMM on H (per batch: A = H[b] 2048x2048, B 2048x256, C 2048x256).
// CTA tile 128 x 256 (full F) x Ktile=32; 8 warps in 2x4 grid, 64x64 per warp.
// TRANSA=1: C[m][f] = scale_m * sum_k A[k][m] B[k][f]   (x_to_E; 1/colsum)
// TRANSA=0: C[m][f] = scale_m * sum_k A[m][k] B[k][f]   (E_to_x; 1/rowsum)
// Norm sums computed in-kernel from staged raw values.
// ===========================================================================
#define BASZ (128 * STR)   // A buffer: 4608 floats
#define BBSZ (256 * STR)   // B buffer: 9216 floats

template <int TRANSA>
__global__ __launch_bounds__(256)
void gemm_big_tc(const float* __restrict__ Hbase, const float* __restrict__ Bmat,
                 float* __restrict__ Cmat) {
    extern __shared__ float sm[];
    float* Abuf = sm;                  // [2][BASZ]
    float* Bbuf = sm + 2 * BASZ;       // [2][BBSZ]
    __shared__ float red[1024];

    int b  = blockIdx.y;
    int m0 = blockIdx.x * 128;
    const float* A  = Hbase + (size_t)b * NN * EE;
    const float* Bp = Bmat  + (size_t)b * 2048 * FF;
    float*       Cp = Cmat  + (size_t)b * 2048 * FF;

    int tid = threadIdx.x, warp = tid >> 5, lane = tid & 31;
    int wm = warp >> 2, wn = warp & 3;   // 2x4 warp grid, 64x64 per warp
    int g = lane >> 2, t = lane & 3;

    uint32_t su   = (uint32_t)__cvta_generic_to_shared(sm);
    uint32_t offA = offA_lane(lane);
    uint32_t offB = offB_lane(lane);

    int mloc  = tid & 127;     // owned m column (TRANSA=1 staging)
    int khalf = tid >> 7;      // 0 or 1

    float acc[4][8][4];
    #pragma unroll
    for (int i = 0; i < 4; ++i)
        #pragma unroll
        for (int j = 0; j < 8; ++j)
            #pragma unroll
            for (int r = 0; r < 4; ++r) acc[i][j][r] = 0.f;

    float4 Ar[4], Br[8];
    float  hsum[4] = {0.f, 0.f, 0.f, 0.f};

    auto load_tile = [&](int k0) {
        #pragma unroll
        for (int r = 0; r < 4; ++r) {
            if (TRANSA) {
                // A gmem [k][m] m-contiguous -> 4x LDG.32 down k (reg transpose)
                int kg = 2 * r + khalf;
                const float* p = &A[(size_t)(k0 + 4 * kg) * EE + m0 + mloc];
                Ar[r].x = p[0]; Ar[r].y = p[EE]; Ar[r].z = p[2 * EE]; Ar[r].w = p[3 * EE];
            } else {
                // A gmem [m][k] k-contiguous -> float4
                int ma = r * 32 + (tid >> 3);
                Ar[r] = *reinterpret_cast<const float4*>(
                    &A[(size_t)(m0 + ma) * EE + k0 + ((tid & 7) << 2)]);
            }
        }
        // B gmem [k][n] n-contiguous; thread owns n=tid, all 32 k (reg transpose)
        #pragma unroll
        for (int r = 0; r < 8; ++r) {
            const float* q = &Bp[(size_t)(k0 + 4 * r) * FF + tid];
            Br[r].x = q[0]; Br[r].y = q[FF]; Br[r].z = q[2 * FF]; Br[r].w = q[3 * FF];
        }
    };

    auto store_tile = [&](int buf) {
        float* Ad = Abuf + buf * BASZ;
        float* Bd = Bbuf + buf * BBSZ;
        #pragma unroll
        for (int r = 0; r < 4; ++r) {
            // raw sums for safe-norm (exactly once per k-tile)
            if (TRANSA) hsum[0] += Ar[r].x + Ar[r].y + Ar[r].z + Ar[r].w;
            else        hsum[r] += Ar[r].x + Ar[r].y + Ar[r].z + Ar[r].w;
            float4 w;
            w.x = tf32r(Ar[r].x); w.y = tf32r(Ar[r].y);
            w.z = tf32r(Ar[r].z); w.w = tf32r(Ar[r].w);
            if (TRANSA) {
                int kg = 2 * r + khalf;
                *reinterpret_cast<float4*>(&Ad[mloc * STR + 4 * kg]) = w;
            } else {
                int ma = r * 32 + (tid >> 3);
                *reinterpret_cast<float4*>(&Ad[ma * STR + ((tid & 7) << 2)]) = w;
            }
        }
        #pragma unroll
        for (int r = 0; r < 8; ++r) {
            float4 w;
            w.x = tf32r(Br[r].x); w.y = tf32r(Br[r].y);
            w.z = tf32r(Br[r].z); w.w = tf32r(Br[r].w);
            *reinterpret_cast<float4*>(&Bd[tid * STR + 4 * r]) = w;
        }
    };

    auto compute = [&](int buf) {
        uint32_t aB = su + (buf * BASZ) * 4;
        uint32_t bB = su + (2 * BASZ + buf * BBSZ) * 4;
        #pragma unroll
        for (int ks = 0; ks < 4; ++ks) {
            uint32_t kkb = ks * 8 * 4;
            uint32_t a[4][4], bb[4][4];
            #pragma unroll
            for (int p = 0; p < 4; ++p)
                ldsm4(bb[p], bB + (uint32_t)((wn * 64 + p * 16) * STR * 4) + kkb + offB);
            #pragma unroll
            for (int mt = 0; mt < 4; ++mt)
                ldsm4(a[mt], aB + (uint32_t)((wm * 64 + mt * 16) * STR * 4) + kkb + offA);
            #pragma unroll
            for (int mt = 0; mt < 4; ++mt)
                #pragma unroll
                for (int nt = 0; nt < 8; ++nt)
                    mma_tf32(acc[mt][nt], a[mt], &bb[nt >> 1][(nt & 1) * 2]);
        }
    };

    const int T = 2048 / 32;
    load_tile(0);
    store_tile(0);
    __syncthreads();
    int buf = 0;
    #pragma unroll 1
    for (int it = 0; it < T; ++it) {
        if (it + 1 < T) load_tile((it + 1) * 32);
        compute(buf);
        if (it + 1 < T) { store_tile(buf ^ 1); __syncthreads(); buf ^= 1; }
    }

    // Reduce norm sums -> red[0..127] = inv scale per local m
    __syncthreads();
    if (TRANSA) {
        red[khalf * 128 + mloc] = hsum[0];
        __syncthreads();
        if (tid < 128) {
            float s = red[tid] + red[128 + tid];
            red[tid] = (s > 0.f) ? (1.f / s) : 0.f;
        }
    } else {
        #pragma unroll
        for (int r = 0; r < 4; ++r)
            red[(tid & 7) * 128 + r * 32 + (tid >> 3)] = hsum[r];
        __syncthreads();
        if (tid < 128) {
            float s = 0.f;
            #pragma unroll
            for (int w = 0; w < 8; ++w) s += red[w * 128 + tid];
            red[tid] = (s > 0.f) ? (1.f / s) : 0.f;
        }
    }
    __syncthreads();

    // Epilogue: per-output-row safe-norm scaling
    #pragma unroll
    for (int mt = 0; mt < 4; ++mt) {
        int ml = wm * 64 + mt * 16 + g;
        int m  = m0 + ml;
        float sc0 = red[ml];
        float sc1 = red[ml + 8];
        #pragma unroll
        for (int nt = 0; nt < 8; ++nt) {
            int n = wn * 64 + nt * 8 + 2 * t;
            float2 v0 = make_float2(acc[mt][nt][0] * sc0, acc[mt][nt][1] * sc0);
            float2 v1 = make_float2(acc[mt][nt][2] * sc1, acc[mt][nt][3] * sc1);
            *reinterpret_cast<float2*>(&Cp[(size_t)m * FF + n]) = v0;
            *reinterpret_cast<float2*>(&Cp[(size_t)(m + 8) * FF + n]) = v1;
        }
    }
}

// ===========================================================================
// Fused small GEMM (R12 known-good path, unchanged).
// C[m][f] = relu( [A1 | A2] @ W + bias ), lda = 256.
// ===========================================================================
#define ASZ (128 * STR)
#define BSZ (128 * STR)

template <bool HAS_A2>
__global__ __launch_bounds__(256, 2)
void gemm_fused_tc(const float* __restrict__ A1, const float* __restrict__ A2,
                   const float* __restrict__ W, const float* __restrict__ bias,
                   float* __restrict__ C) {
    extern __shared__ float sm[];
    float* Abuf = sm;
    float* Bbuf = sm + 2 * ASZ;

    int m0 = blockIdx.y * 128, n0 = blockIdx.x * 128;
    int tid = threadIdx.x, warp = tid >> 5, lane = tid & 31;
    int wm = warp >> 2, wn = warp & 3;
    int g = lane >> 2, t = lane & 3;

    uint32_t su   = (uint32_t)__cvta_generic_to_shared(sm);
    uint32_t offA = offA_lane(lane);
    uint32_t offB = offB_lane(lane);

    int nloc  = tid & 127;
    int khalf = tid >> 7;

    float acc[4][4][4];
    #pragma unroll
    for (int i = 0; i < 4; ++i)
        #pragma unroll
        for (int j = 0; j < 4; ++j)
            #pragma unroll
            for (int r = 0; r < 4; ++r) acc[i][j][r] = 0.f;

    float4 Ar[4], Br[4];

    auto load_tile = [&](int k0) {
        const float* Asrc = (!HAS_A2 || k0 < 256) ? A1 : A2;
        int kloc = (!HAS_A2 || k0 < 256) ? k0 : (k0 - 256);
        #pragma unroll
        for (int r = 0; r < 4; ++r) {
            int ma = r * 32 + (tid >> 3), ca = (tid & 7) << 2;
            Ar[r] = *reinterpret_cast<const float4*>(&Asrc[(size_t)(m0 + ma) * FF + kloc + ca]);
            int kg = 2 * r + khalf;
            const float* q = &W[(size_t)(k0 + 4 * kg) * FF + n0 + nloc];
            Br[r].x = q[0]; Br[r].y = q[FF]; Br[r].z = q[2 * FF]; Br[r].w = q[3 * FF];
        }
    };

    auto store_tile = [&](int buf) {
        float* Ad = Abuf + buf * ASZ;
        float* Bd = Bbuf + buf * BSZ;
        #pragma unroll
        for (int r = 0; r < 4; ++r) {
            float4 w;
            w.x = tf32r(Ar[r].x); w.y = tf32r(Ar[r].y);
            w.z = tf32r(Ar[r].z); w.w = tf32r(Ar[r].w);
            int ma = r * 32 + (tid >> 3), ca = (tid & 7) << 2;
            *reinterpret_cast<float4*>(&Ad[ma * STR + ca]) = w;
            float4 xv;
            xv.x = tf32r(Br[r].x); xv.y = tf32r(Br[r].y);
            xv.z = tf32r(Br[r].z); xv.w = tf32r(Br[r].w);
            int kg = 2 * r + khalf;
            *reinterpret_cast<float4*>(&Bd[nloc * STR + 4 * kg]) = xv;
        }
    };

    auto compute = [&](int buf) {
        uint32_t aB = su + (buf * ASZ) * 4;
        uint32_t bB = su + (2 * ASZ + buf * BSZ) * 4;
        #pragma unroll
        for (int ks = 0; ks < 4; ++ks) {
            uint32_t kkb = ks * 8 * 4;
            uint32_t a[4][4], bb[2][4];
            #pragma unroll
            for (int p = 0; p < 2; ++p)
                ldsm4(bb[p], bB + (uint32_t)((wn * 32 + p * 16) * STR * 4) + kkb + offB);
            #pragma unroll
            for (int mt = 0; mt < 4; ++mt)
                ldsm4(a[mt], aB + (uint32_t)((wm * 64 + mt * 16) * STR * 4) + kkb + offA);
            #pragma unroll
            for (int mt = 0; mt < 4; ++mt) {
                mma_tf32(acc[mt][0], a[mt], &bb[0][0]);
                mma_tf32(acc[mt][1], a[mt], &bb[0][2]);
                mma_tf32(acc[mt][2], a[mt], &bb[1][0]);
                mma_tf32(acc[mt][3], a[mt], &bb[1][2]);
            }
        }
    };

    const int K = HAS_A2 ? 512 : 256;
    const int T = K / 32;
    load_tile(0);
    store_tile(0);
    __syncthreads();
    int buf = 0;
    #pragma unroll 1
    for (int it = 0; it < T; ++it) {
        if (it + 1 < T) load_tile((it + 1) * 32);
        compute(buf);
        if (it + 1 < T) { store_tile(buf ^ 1); __syncthreads(); buf ^= 1; }
    }

    #pragma unroll
    for (int nt = 0; nt < 4; ++nt) {
        int n = n0 + wn * 32 + nt * 8 + 2 * t;
        float bv0 = bias[n], bv1 = bias[n + 1];
        #pragma unroll
        for (int mt = 0; mt < 4; ++mt) {
            int m = m0 + wm * 64 + mt * 16 + g;
            float2 v0 = make_float2(fmaxf(acc[mt][nt][0] + bv0, 0.f),
                                    fmaxf(acc[mt][nt][1] + bv1, 0.f));
            float2 v1 = make_float2(fmaxf(acc[mt][nt][2] + bv0, 0.f),
                                    fmaxf(acc[mt][nt][3] + bv1, 0.f));
            *reinterpret_cast<float2*>(&C[(size_t)m * FF + n]) = v0;
            *reinterpret_cast<float2*>(&C[(size_t)(m + 8) * FF + n]) = v1;
        }
    }
}

// ---------------------------------------------------------------------------
extern "C" void kernel_launch(void* const* d_in, const int* in_sizes, int n_in,
                              void* d_out, int out_size) {
    const float* H    = (const float*)d_in[0];
    const float* E    = (const float*)d_in[1];
    const float* x    = (const float*)d_in[2];
    const float* W_ne = (const float*)d_in[3];
    const float* b_ne = (const float*)d_in[4];
    const float* W_e  = (const float*)d_in[5];
    const float* b_e  = (const float*)d_in[6];
    const float* W_n  = (const float*)d_in[7];
    const float* b_n  = (const float*)d_in[8];

    float* out  = (float*)d_out;
    float* newE = out;
    float* newx = out + (size_t)BATCH * EE * FF;

    float* scratch = nullptr;
    cudaGetSymbolAddress((void**)&scratch, g_scratch);
    float* ne   = scratch;
    float* xtoE = scratch + 8388608;
    float* EtoX = scratch + 16777216;

    const int SMEM_BIG   = (2 * BASZ + 2 * BBSZ) * 4;   // 110592 bytes
    const int SMEM_FUSED = (2 * ASZ + 2 * BSZ) * 4;     // 73728 bytes

    static bool attr_done = false;
    if (!attr_done) {
        cudaFuncSetAttribute(gemm_big_tc<1>, cudaFuncAttributeMaxDynamicSharedMemorySize, SMEM_BIG);
        cudaFuncSetAttribute(gemm_big_tc<0>, cudaFuncAttributeMaxDynamicSharedMemorySize, SMEM_BIG);
        cudaFuncSetAttribute(gemm_fused_tc<false>, cudaFuncAttributeMaxDynamicSharedMemorySize, SMEM_FUSED);
        cudaFuncSetAttribute(gemm_fused_tc<true>, cudaFuncAttributeMaxDynamicSharedMemorySize, SMEM_FUSED);
        attr_done = true;
    }

    // 1) ne = relu(x @ W_ne + b_ne)
    gemm_fused_tc<false><<<dim3(FF / 128, BATCH * NN / 128), 256, SMEM_FUSED>>>(
        x, nullptr, W_ne, b_ne, ne);

    // 2) x_to_E = colscale * (H^T @ ne)   [colsum fused in-kernel]
    gemm_big_tc<1><<<dim3(EE / 128, BATCH), 256, SMEM_BIG>>>(H, ne, xtoE);

    // 3) new_E = relu([x_to_E, E] @ W_e + b_e)
    gemm_fused_tc<true><<<dim3(FF / 128, BATCH * EE / 128), 256, SMEM_FUSED>>>(
        xtoE, E, W_e, b_e, newE);

    // 4) E_to_x = rowscale * (H @ new_E)  [rowsum fused in-kernel]
    gemm_big_tc<0><<<dim3(NN / 128, BATCH), 256, SMEM_BIG>>>(H, newE, EtoX);

    // 5) new_x = relu([E_to_x, x] @ W_n + b_n)
    gemm_fused_tc<true><<<dim3(FF / 128, BATCH * NN / 128), 256, SMEM_FUSED>>>(
        EtoX, x, W_n, b_n, newx);
}

// round 16
// speedup vs baseline: 4.3012x; 1.0357x over previous
#include <cuda_runtime.h>
#include <cstdint>

// Problem dims
#define BATCH 16
#define NN    2048
#define EE    2048
#define FF    256

// Scratch layout (floats):
//   xtoE  : 8M   @ 0
//   EtoX  : 8M   @ 8388608
//   neT   : 8M   @ 16777216   (tf32, [b][f][node])
//   newET : 8M   @ 25165824   (tf32, [b][f][e])
//   WneT  : 64K  @ 33554432   (tf32, [f][k], k=256)
//   WeT   : 128K @ 33619968   (tf32, [f][k], k=512)
//   WnT   : 128K @ 33751040   (tf32, [f][k], k=512)
__device__ float g_scratch[33882112];

// ---------------------------------------------------------------------------
#define STR 36   // smem row stride (floats); 36 ≡ 4 mod 32 -> conflict-free

__device__ __forceinline__ float tf32r(float x) {
    unsigned u;
    asm("cvt.rna.tf32.f32 %0, %1;" : "=r"(u) : "f"(x));
    return __uint_as_float(u);
}

__device__ __forceinline__ void ldsm4(uint32_t* d, uint32_t addr) {
    asm volatile("ldmatrix.sync.aligned.m8n8.x4.shared.b16 {%0,%1,%2,%3}, [%4];"
                 : "=r"(d[0]), "=r"(d[1]), "=r"(d[2]), "=r"(d[3]) : "r"(addr));
}

__device__ __forceinline__ void mma_tf32(float* c, const uint32_t* a, const uint32_t* b) {
    asm volatile(
        "mma.sync.aligned.m16n8k8.row.col.f32.tf32.tf32.f32 "
        "{%0,%1,%2,%3}, {%4,%5,%6,%7}, {%8,%9}, {%0,%1,%2,%3};\n"
        : "+f"(c[0]), "+f"(c[1]), "+f"(c[2]), "+f"(c[3])
        : "r"(a[0]), "r"(a[1]), "r"(a[2]), "r"(a[3]), "r"(b[0]), "r"(b[1]));
}

__device__ __forceinline__ uint32_t offA_lane(int lane) {
    return (uint32_t)(((lane & 15) * STR + (lane >> 4) * 4) * 4);
}
__device__ __forceinline__ uint32_t offB_lane(int lane) {
    return (uint32_t)((((lane >> 4) * 8 + (lane & 7)) * STR + ((lane >> 3) & 1) * 4) * 4);
}

// ---------------------------------------------------------------------------
// Weight prep: WT[f][k] = tf32(W[k][f])  (one tiny launch)
// ---------------------------------------------------------------------------
__global__ void prep_weights(const float* __restrict__ Wne, const float* __restrict__ We,
                             const float* __restrict__ Wn, float* __restrict__ WneT,
                             float* __restrict__ WeT, float* __restrict__ WnT) {
    int idx = blockIdx.x * 256 + threadIdx.x;
    if (idx < 65536) {
        int f = idx >> 8, k = idx & 255;
        WneT[f * 256 + k] = tf32r(Wne[k * 256 + f]);
        return;
    }
    idx -= 65536;
    if (idx < 131072) {
        int f = idx >> 9, k = idx & 511;
        WeT[f * 512 + k] = tf32r(We[k * 256 + f]);
        return;
    }
    idx -= 131072;
    int f = idx >> 9, k = idx & 511;
    WnT[f * 512 + k] = tf32r(Wn[k * 256 + f]);
}

// ===========================================================================
// Big GEMM on H (per batch: A = H[b] 2048x2048, BT tf32 [256][2048], C 2048x256)
// CTA tile 128 x 256 x Ktile=32; 8 warps 2x4, 64x64 per warp.
// TRANSA=1: C[m][f] = scale_m * sum_k A[k][m] BT[f][k]   (x_to_E; 1/colsum)
// TRANSA=0: C[m][f] = scale_m * sum_k A[m][k] BT[f][k]   (E_to_x; 1/rowsum)
// ===========================================================================
#define BASZ (128 * STR)
#define BBSZ (256 * STR)

template <int TRANSA>
__global__ __launch_bounds__(256)
void gemm_big_tc(const float* __restrict__ Hbase, const float* __restrict__ BTmat,
                 float* __restrict__ Cmat) {
    extern __shared__ float sm[];
    float* Abuf = sm;                  // [2][BASZ]
    float* Bbuf = sm + 2 * BASZ;       // [2][BBSZ]
    __shared__ float red[1024];

    int b  = blockIdx.y;
    int m0 = blockIdx.x * 128;
    const float* A  = Hbase + (size_t)b * NN * EE;
    const float* BT = BTmat + (size_t)b * FF * 2048;   // [f][k] tf32
    float*       Cp = Cmat  + (size_t)b * 2048 * FF;

    int tid = threadIdx.x, warp = tid >> 5, lane = tid & 31;
    int wm = warp >> 2, wn = warp & 3;
    int g = lane >> 2, t = lane & 3;

    uint32_t su   = (uint32_t)__cvta_generic_to_shared(sm);
    uint32_t offA = offA_lane(lane);
    uint32_t offB = offB_lane(lane);

    int mloc  = tid & 127;
    int khalf = tid >> 7;

    float acc[4][8][4];
    #pragma unroll
    for (int i = 0; i < 4; ++i)
        #pragma unroll
        for (int j = 0; j < 8; ++j)
            #pragma unroll
            for (int r = 0; r < 4; ++r) acc[i][j][r] = 0.f;

    float4 Ar[4], Br[8];
    float  hsum[4] = {0.f, 0.f, 0.f, 0.f};

    auto load_tile = [&](int k0) {
        #pragma unroll
        for (int r = 0; r < 4; ++r) {
            if (TRANSA) {
                int kg = 2 * r + khalf;
                const float* p = &A[(size_t)(k0 + 4 * kg) * EE + m0 + mloc];
                Ar[r].x = p[0]; Ar[r].y = p[EE]; Ar[r].z = p[2 * EE]; Ar[r].w = p[3 * EE];
            } else {
                int ma = r * 32 + (tid >> 3);
                Ar[r] = *reinterpret_cast<const float4*>(
                    &A[(size_t)(m0 + ma) * EE + k0 + ((tid & 7) << 2)]);
            }
        }
        // BT is [f][k] tf32, k-contiguous: plain float4 loads
        #pragma unroll
        for (int r = 0; r < 8; ++r) {
            int row = r * 32 + (tid >> 3);
            Br[r] = *reinterpret_cast<const float4*>(
                &BT[(size_t)row * 2048 + k0 + ((tid & 7) << 2)]);
        }
    };

    auto store_tile = [&](int buf) {
        float* Ad = Abuf + buf * BASZ;
        float* Bd = Bbuf + buf * BBSZ;
        #pragma unroll
        for (int r = 0; r < 4; ++r) {
            if (TRANSA) hsum[0] += Ar[r].x + Ar[r].y + Ar[r].z + Ar[r].w;
            else        hsum[r] += Ar[r].x + Ar[r].y + Ar[r].z + Ar[r].w;
            float4 w;
            w.x = tf32r(Ar[r].x); w.y = tf32r(Ar[r].y);
            w.z = tf32r(Ar[r].z); w.w = tf32r(Ar[r].w);
            if (TRANSA) {
                int kg = 2 * r + khalf;
                *reinterpret_cast<float4*>(&Ad[mloc * STR + 4 * kg]) = w;
            } else {
                int ma = r * 32 + (tid >> 3);
                *reinterpret_cast<float4*>(&Ad[ma * STR + ((tid & 7) << 2)]) = w;
            }
        }
        #pragma unroll
        for (int r = 0; r < 8; ++r) {
            int row = r * 32 + (tid >> 3);
            *reinterpret_cast<float4*>(&Bd[row * STR + ((tid & 7) << 2)]) = Br[r];
        }
    };

    auto compute_part = [&](int buf, int s0, int s1) {
        uint32_t aB = su + (buf * BASZ) * 4;
        uint32_t bB = su + (2 * BASZ + buf * BBSZ) * 4;
        #pragma unroll
        for (int ks = s0; ks < s1; ++ks) {
            uint32_t kkb = ks * 8 * 4;
            uint32_t a[4][4], bb[4][4];
            #pragma unroll
            for (int p = 0; p < 4; ++p)
                ldsm4(bb[p], bB + (uint32_t)((wn * 64 + p * 16) * STR * 4) + kkb + offB);
            #pragma unroll
            for (int mt = 0; mt < 4; ++mt)
                ldsm4(a[mt], aB + (uint32_t)((wm * 64 + mt * 16) * STR * 4) + kkb + offA);
            #pragma unroll
            for (int mt = 0; mt < 4; ++mt)
                #pragma unroll
                for (int nt = 0; nt < 8; ++nt)
                    mma_tf32(acc[mt][nt], a[mt], &bb[nt >> 1][(nt & 1) * 2]);
        }
    };

    const int T = 2048 / 32;
    load_tile(0);
    store_tile(0);
    __syncthreads();
    int buf = 0;
    #pragma unroll 1
    for (int it = 0; it < T; ++it) {
        if (it + 1 < T) load_tile((it + 1) * 32);
        compute_part(buf, 0, 3);
        if (it + 1 < T) store_tile(buf ^ 1);
        compute_part(buf, 3, 4);
        if (it + 1 < T) { __syncthreads(); buf ^= 1; }
    }

    // Reduce norm sums -> red[0..127] = inv scale per local m
    __syncthreads();
    if (TRANSA) {
        red[khalf * 128 + mloc] = hsum[0];
        __syncthreads();
        if (tid < 128) {
            float s = red[tid] + red[128 + tid];
            red[tid] = (s > 0.f) ? (1.f / s) : 0.f;
        }
    } else {
        #pragma unroll
        for (int r = 0; r < 4; ++r)
            red[(tid & 7) * 128 + r * 32 + (tid >> 3)] = hsum[r];
        __syncthreads();
        if (tid < 128) {
            float s = 0.f;
            #pragma unroll
            for (int w = 0; w < 8; ++w) s += red[w * 128 + tid];
            red[tid] = (s > 0.f) ? (1.f / s) : 0.f;
        }
    }
    __syncthreads();

    // Epilogue: per-output-row safe-norm scaling
    #pragma unroll
    for (int mt = 0; mt < 4; ++mt) {
        int ml = wm * 64 + mt * 16 + g;
        int m  = m0 + ml;
        float sc0 = red[ml];
        float sc1 = red[ml + 8];
        #pragma unroll
        for (int nt = 0; nt < 8; ++nt) {
            int n = wn * 64 + nt * 8 + 2 * t;
            float2 v0 = make_float2(acc[mt][nt][0] * sc0, acc[mt][nt][1] * sc0);
            float2 v1 = make_float2(acc[mt][nt][2] * sc1, acc[mt][nt][3] * sc1);
            *reinterpret_cast<float2*>(&Cp[(size_t)m * FF + n]) = v0;
            *reinterpret_cast<float2*>(&Cp[(size_t)(m + 8) * FF + n]) = v1;
        }
    }
}

// ===========================================================================
// Fused small GEMM: relu([A1|A2] @ W + bias); W pre-transposed tf32 [f][KTOT].
// TOUT=0: normal f32 out. TOUT=1: transposed tf32 out only ([b][f][m%2048]).
// TOUT=2: both (normal to Cn, transposed tf32 to Ct).
// ===========================================================================
#define ASZ (128 * STR)
#define BSZ (128 * STR)

template <int KTOT, int TOUT>
__global__ __launch_bounds__(256, 2)
void gemm_fused_tc(const float* __restrict__ A1, const float* __restrict__ A2,
                   const float* __restrict__ WT, const float* __restrict__ bias,
                   float* __restrict__ Cn, float* __restrict__ Ct) {
    extern __shared__ float sm[];
    float* Abuf = sm;
    float* Bbuf = sm + 2 * ASZ;

    int m0 = blockIdx.y * 128, n0 = blockIdx.x * 128;
    int tid = threadIdx.x, warp = tid >> 5, lane = tid & 31;
    int wm = warp >> 2, wn = warp & 3;
    int g = lane >> 2, t = lane & 3;

    uint32_t su   = (uint32_t)__cvta_generic_to_shared(sm);
    uint32_t offA = offA_lane(lane);
    uint32_t offB = offB_lane(lane);

    float acc[4][4][4];
    #pragma unroll
    for (int i = 0; i < 4; ++i)
        #pragma unroll
        for (int j = 0; j < 4; ++j)
            #pragma unroll
            for (int r = 0; r < 4; ++r) acc[i][j][r] = 0.f;

    float4 Ar[4], Br[4];

    auto load_tile = [&](int k0) {
        const float* Asrc = (KTOT == 256 || k0 < 256) ? A1 : A2;
        int kloc = (KTOT == 256 || k0 < 256) ? k0 : (k0 - 256);
        #pragma unroll
        for (int r = 0; r < 4; ++r) {
            int ma = r * 32 + (tid >> 3), ca = (tid & 7) << 2;
            Ar[r] = *reinterpret_cast<const float4*>(&Asrc[(size_t)(m0 + ma) * FF + kloc + ca]);
            // WT [f][KTOT] k-contiguous tf32
            Br[r] = *reinterpret_cast<const float4*>(&WT[(size_t)(n0 + ma) * KTOT + k0 + ca]);
        }
    };

    auto store_tile = [&](int buf) {
        float* Ad = Abuf + buf * ASZ;
        float* Bd = Bbuf + buf * BSZ;
        #pragma unroll
        for (int r = 0; r < 4; ++r) {
            float4 w;
            w.x = tf32r(Ar[r].x); w.y = tf32r(Ar[r].y);
            w.z = tf32r(Ar[r].z); w.w = tf32r(Ar[r].w);
            int ma = r * 32 + (tid >> 3), ca = (tid & 7) << 2;
            *reinterpret_cast<float4*>(&Ad[ma * STR + ca]) = w;
            *reinterpret_cast<float4*>(&Bd[ma * STR + ca]) = Br[r];
        }
    };

    auto compute_part = [&](int buf, int s0, int s1) {
        uint32_t aB = su + (buf * ASZ) * 4;
        uint32_t bB = su + (2 * ASZ + buf * BSZ) * 4;
        #pragma unroll
        for (int ks = s0; ks < s1; ++ks) {
            uint32_t kkb = ks * 8 * 4;
            uint32_t a[4][4], bb[2][4];
            #pragma unroll
            for (int p = 0; p < 2; ++p)
                ldsm4(bb[p], bB + (uint32_t)((wn * 32 + p * 16) * STR * 4) + kkb + offB);
            #pragma unroll
            for (int mt = 0; mt < 4; ++mt)
                ldsm4(a[mt], aB + (uint32_t)((wm * 64 + mt * 16) * STR * 4) + kkb + offA);
            #pragma unroll
            for (int mt = 0; mt < 4; ++mt) {
                mma_tf32(acc[mt][0], a[mt], &bb[0][0]);
                mma_tf32(acc[mt][1], a[mt], &bb[0][2]);
                mma_tf32(acc[mt][2], a[mt], &bb[1][0]);
                mma_tf32(acc[mt][3], a[mt], &bb[1][2]);
            }
        }
    };

    const int T = KTOT / 32;
    load_tile(0);
    store_tile(0);
    __syncthreads();
    int buf = 0;
    #pragma unroll 1
    for (int it = 0; it < T; ++it) {
        if (it + 1 < T) load_tile((it + 1) * 32);
        compute_part(buf, 0, 3);
        if (it + 1 < T) store_tile(buf ^ 1);
        compute_part(buf, 3, 4);
        if (it + 1 < T) { __syncthreads(); buf ^= 1; }
    }

    // Epilogue: bias + relu (+ optional transposed tf32 write)
    #pragma unroll
    for (int nt = 0; nt < 4; ++nt) {
        int n = n0 + wn * 32 + nt * 8 + 2 * t;
        float bv0 = bias[n], bv1 = bias[n + 1];
        #pragma unroll
        for (int mt = 0; mt < 4; ++mt) {
            int m = m0 + wm * 64 + mt * 16 + g;
            float2 v0 = make_float2(fmaxf(acc[mt][nt][0] + bv0, 0.f),
                                    fmaxf(acc[mt][nt][1] + bv1, 0.f));
            float2 v1 = make_float2(fmaxf(acc[mt][nt][2] + bv0, 0.f),
                                    fmaxf(acc[mt][nt][3] + bv1, 0.f));
            if (TOUT != 1) {
                *reinterpret_cast<float2*>(&Cn[(size_t)m * FF + n]) = v0;
                *reinterpret_cast<float2*>(&Cn[(size_t)(m + 8) * FF + n]) = v1;
            }
            if (TOUT != 0) {
                int batch = m >> 11, node = m & 2047;
                float* Tb = Ct + (size_t)batch * FF * 2048;
                Tb[(size_t)n * 2048 + node]             = tf32r(v0.x);
                Tb[(size_t)(n + 1) * 2048 + node]       = tf32r(v0.y);
                Tb[(size_t)n * 2048 + node + 8]         = tf32r(v1.x);
                Tb[(size_t)(n + 1) * 2048 + node + 8]   = tf32r(v1.y);
            }
        }
    }
}

// ---------------------------------------------------------------------------
extern "C" void kernel_launch(void* const* d_in, const int* in_sizes, int n_in,
                              void* d_out, int out_size) {
    const float* H    = (const float*)d_in[0];
    const float* E    = (const float*)d_in[1];
    const float* x    = (const float*)d_in[2];
    const float* W_ne = (const float*)d_in[3];
    const float* b_ne = (const float*)d_in[4];
    const float* W_e  = (const float*)d_in[5];
    const float* b_e  = (const float*)d_in[6];
    const float* W_n  = (const float*)d_in[7];
    const float* b_n  = (const float*)d_in[8];

    float* out  = (float*)d_out;
    float* newE = out;
    float* newx = out + (size_t)BATCH * EE * FF;

    float* scratch = nullptr;
    cudaGetSymbolAddress((void**)&scratch, g_scratch);
    float* xtoE  = scratch;
    float* EtoX  = scratch + 8388608;
    float* neT   = scratch + 16777216;
    float* newET = scratch + 25165824;
    float* WneT  = scratch + 33554432;
    float* WeT   = scratch + 33619968;
    float* WnT   = scratch + 33751040;

    const int SMEM_BIG   = (2 * BASZ + 2 * BBSZ) * 4;   // 110592
    const int SMEM_FUSED = (2 * ASZ + 2 * BSZ) * 4;     // 73728

    static bool attr_done = false;
    if (!attr_done) {
        cudaFuncSetAttribute(gemm_big_tc<1>, cudaFuncAttributeMaxDynamicSharedMemorySize, SMEM_BIG);
        cudaFuncSetAttribute(gemm_big_tc<0>, cudaFuncAttributeMaxDynamicSharedMemorySize, SMEM_BIG);
        cudaFuncSetAttribute(gemm_fused_tc<256, 1>, cudaFuncAttributeMaxDynamicSharedMemorySize, SMEM_FUSED);
        cudaFuncSetAttribute(gemm_fused_tc<512, 2>, cudaFuncAttributeMaxDynamicSharedMemorySize, SMEM_FUSED);
        cudaFuncSetAttribute(gemm_fused_tc<512, 0>, cudaFuncAttributeMaxDynamicSharedMemorySize, SMEM_FUSED);
        attr_done = true;
    }

    // 0) transpose + tf32-convert weights
    prep_weights<<<1280, 256>>>(W_ne, W_e, W_n, WneT, WeT, WnT);

    // 1) neT = tf32(relu(x @ W_ne + b_ne))^T
    gemm_fused_tc<256, 1><<<dim3(FF / 128, BATCH * NN / 128), 256, SMEM_FUSED>>>(
        x, nullptr, WneT, b_ne, nullptr, neT);

    // 2) x_to_E = colscale * (H^T @ ne)   [colsum fused in-kernel]
    gemm_big_tc<1><<<dim3(EE / 128, BATCH), 256, SMEM_BIG>>>(H, neT, xtoE);

    // 3) new_E = relu([x_to_E, E] @ W_e + b_e)  (+ transposed tf32 copy)
    gemm_fused_tc<512, 2><<<dim3(FF / 128, BATCH * EE / 128), 256, SMEM_FUSED>>>(
        xtoE, E, WeT, b_e, newE, newET);

    // 4) E_to_x = rowscale * (H @ new_E)  [rowsum fused in-kernel]
    gemm_big_tc<0><<<dim3(NN / 128, BATCH), 256, SMEM_BIG>>>(H, newET, EtoX);

    // 5) new_x = relu([E_to_x, x] @ W_n + b_n)
    gemm_fused_tc<512, 0><<<dim3(FF / 128, BATCH * NN / 128), 256, SMEM_FUSED>>>(
        EtoX, x, WnT, b_n, newx, nullptr);
}